// round 8
// baseline (speedup 1.0000x reference)
#include <cuda_runtime.h>
#include <cuda_fp16.h>
#include <cstdint>

// Problem constants (fixed shapes for this dataset)
#define BATCH   4
#define NPTS    16384
#define MPTS    4096
#define C1DIM   128
#define C2DIM   256
#define CIN     384       // C1 + C2
#define H1DIM   256
#define H2DIM   256
#define COUT    128
#define TOTAL   (BATCH * NPTS)   // 65536 points

// ---------------------------------------------------------------------------
// Scratch (static device globals — no runtime allocation allowed)
// ---------------------------------------------------------------------------
__device__ int   g_idx[TOTAL * 3];
__device__ float g_w[TOTAL * 3];
__device__ __align__(256) __half g_Xh[(size_t)TOTAL * CIN];
__device__ __align__(256) __half g_Xl[(size_t)TOTAL * CIN];
__device__ __align__(256) __half g_Hah[(size_t)TOTAL * H1DIM];
__device__ __align__(256) __half g_Hal[(size_t)TOTAL * H1DIM];
__device__ __align__(256) __half g_Hbh[(size_t)TOTAL * H2DIM];
__device__ __align__(256) __half g_Hbl[(size_t)TOTAL * H2DIM];
__device__ __align__(256) __half g_W1h[H1DIM * CIN];
__device__ __align__(256) __half g_W2h[H2DIM * H1DIM];
__device__ __align__(256) __half g_W3h[COUT * H2DIM];
__device__ __align__(256) __half g_W3l[COUT * H2DIM];

// ---------------------------------------------------------------------------
// Small helpers
// ---------------------------------------------------------------------------
__device__ __forceinline__ uint32_t smem_to_u32(const void* p) {
    uint32_t a;
    asm("{ .reg .u64 t; cvta.to.shared.u64 t, %1; cvt.u32.u64 %0, t; }"
        : "=r"(a) : "l"(p));
    return a;
}
__device__ __forceinline__ void cpa16(uint32_t dst, const void* src) {
    asm volatile("cp.async.cg.shared.global [%0], [%1], 16;"
                 :: "r"(dst), "l"(src));
}
__device__ __forceinline__ void cpa_commit() {
    asm volatile("cp.async.commit_group;" ::: "memory");
}
template <int N>
__device__ __forceinline__ void cpa_wait() {
    asm volatile("cp.async.wait_group %0;" :: "n"(N) : "memory");
}
__device__ __forceinline__ void ldsm_x4(uint32_t* r, uint32_t addr) {
    asm volatile("ldmatrix.sync.aligned.m8n8.x4.shared.b16 {%0,%1,%2,%3}, [%4];"
                 : "=r"(r[0]), "=r"(r[1]), "=r"(r[2]), "=r"(r[3]) : "r"(addr));
}
// m16n8k16 row.col fp16 MMA, f32 accumulate
__device__ __forceinline__ void mma_f16(float* d, const uint32_t* a,
                                        const uint32_t* b) {
    asm("mma.sync.aligned.m16n8k16.row.col.f32.f16.f16.f32 "
        "{%0,%1,%2,%3}, {%4,%5,%6,%7}, {%8,%9}, {%0,%1,%2,%3};"
        : "+f"(d[0]), "+f"(d[1]), "+f"(d[2]), "+f"(d[3])
        : "r"(a[0]), "r"(a[1]), "r"(a[2]), "r"(a[3]), "r"(b[0]), "r"(b[1]));
}
// fp32 -> fp16 hi/lo split
__device__ __forceinline__ void split_f16(float x, __half& h, __half& l) {
    h = __float2half_rn(x);
    l = __float2half_rn(x - __half2float(h));
}
// packed f32x2 helpers (sm_100+; proven on this harness)
__device__ __forceinline__ unsigned long long pk2(float a, float b) {
    unsigned long long r;
    asm("mov.b64 %0, {%1, %2};" : "=l"(r)
        : "r"(__float_as_uint(a)), "r"(__float_as_uint(b)));
    return r;
}
__device__ __forceinline__ unsigned long long add2(unsigned long long a,
                                                   unsigned long long b) {
    unsigned long long r;
    asm("add.rn.f32x2 %0, %1, %2;" : "=l"(r) : "l"(a), "l"(b));
    return r;
}
__device__ __forceinline__ unsigned long long mul2(unsigned long long a,
                                                   unsigned long long b) {
    unsigned long long r;
    asm("mul.rn.f32x2 %0, %1, %2;" : "=l"(r) : "l"(a), "l"(b));
    return r;
}
__device__ __forceinline__ unsigned long long fma2(unsigned long long a,
                                                   unsigned long long b,
                                                   unsigned long long c) {
    unsigned long long r;
    asm("fma.rn.f32x2 %0, %1, %2, %3;" : "=l"(r) : "l"(a), "l"(b), "l"(c));
    return r;
}
__device__ __forceinline__ void unpk2(unsigned long long v, float& lo, float& hi) {
    uint32_t a, b;
    asm("mov.b64 {%0, %1}, %2;" : "=r"(a), "=r"(b) : "l"(v));
    lo = __uint_as_float(a);
    hi = __uint_as_float(b);
}

// ---------------------------------------------------------------------------
// Kernel 1: three_nn + interpolation weights. 2 query points per thread.
// ---------------------------------------------------------------------------
__device__ __forceinline__ void upd3(float d, int j,
                                     float& d0, float& d1, float& d2,
                                     int& i0, int& i1, int& i2) {
    if (d < d2) {
        if (d < d1) {
            d2 = d1; i2 = i1;
            if (d < d0) { d1 = d0; i1 = i0; d0 = d; i0 = j; }
            else        { d1 = d;  i1 = j; }
        } else {
            d2 = d; i2 = j;
        }
    }
}

__global__ __launch_bounds__(256) void three_nn_kernel(
    const float* __restrict__ xyz1, const float* __restrict__ xyz2)
{
    // negated xyz2 coords, accessed as packed float pairs
    __shared__ __align__(8) float snx[MPTS];
    __shared__ __align__(8) float sny[MPTS];
    __shared__ __align__(8) float snz[MPTS];

    const int b = blockIdx.y;
    const float* p2 = xyz2 + (size_t)b * MPTS * 3;
    for (int j = threadIdx.x; j < MPTS; j += 256) {
        snx[j] = -p2[3 * j + 0];
        sny[j] = -p2[3 * j + 1];
        snz[j] = -p2[3 * j + 2];
    }
    __syncthreads();

    const int nA = blockIdx.x * 512 + threadIdx.x;
    const int nB = nA + 256;
    const float* pA = xyz1 + ((size_t)b * NPTS + nA) * 3;
    const float* pB = xyz1 + ((size_t)b * NPTS + nB) * 3;
    const unsigned long long xA = pk2(pA[0], pA[0]);
    const unsigned long long yA = pk2(pA[1], pA[1]);
    const unsigned long long zA = pk2(pA[2], pA[2]);
    const unsigned long long xB = pk2(pB[0], pB[0]);
    const unsigned long long yB = pk2(pB[1], pB[1]);
    const unsigned long long zB = pk2(pB[2], pB[2]);

    float d0A = 1e30f, d1A = 1e30f, d2A = 1e30f;
    int   i0A = 0, i1A = 0, i2A = 0;
    float d0B = 1e30f, d1B = 1e30f, d2B = 1e30f;
    int   i0B = 0, i1B = 0, i2B = 0;

    const unsigned long long* nxp = (const unsigned long long*)snx;
    const unsigned long long* nyp = (const unsigned long long*)sny;
    const unsigned long long* nzp = (const unsigned long long*)snz;

#pragma unroll 4
    for (int p = 0; p < MPTS / 2; p++) {
        const unsigned long long cx = nxp[p];
        const unsigned long long cy = nyp[p];
        const unsigned long long cz = nzp[p];
        unsigned long long dxA = add2(xA, cx);
        unsigned long long dyA = add2(yA, cy);
        unsigned long long dzA = add2(zA, cz);
        unsigned long long ddA = mul2(dxA, dxA);
        ddA = fma2(dyA, dyA, ddA);
        ddA = fma2(dzA, dzA, ddA);
        unsigned long long dxB = add2(xB, cx);
        unsigned long long dyB = add2(yB, cy);
        unsigned long long dzB = add2(zB, cz);
        unsigned long long ddB = mul2(dxB, dxB);
        ddB = fma2(dyB, dyB, ddB);
        ddB = fma2(dzB, dzB, ddB);
        float loA, hiA, loB, hiB;
        unpk2(ddA, loA, hiA);
        unpk2(ddB, loB, hiB);
        if (fminf(loA, hiA) < d2A) {
            upd3(loA, 2 * p,     d0A, d1A, d2A, i0A, i1A, i2A);
            upd3(hiA, 2 * p + 1, d0A, d1A, d2A, i0A, i1A, i2A);
        }
        if (fminf(loB, hiB) < d2B) {
            upd3(loB, 2 * p,     d0B, d1B, d2B, i0B, i1B, i2B);
            upd3(hiB, 2 * p + 1, d0B, d1B, d2B, i0B, i1B, i2B);
        }
    }

    {
        float r0 = 1.0f / fmaxf(d0A, 1e-10f);
        float r1 = 1.0f / fmaxf(d1A, 1e-10f);
        float r2 = 1.0f / fmaxf(d2A, 1e-10f);
        float s = 1.0f / (r0 + r1 + r2);
        size_t o = ((size_t)b * NPTS + nA) * 3;
        g_idx[o + 0] = i0A; g_idx[o + 1] = i1A; g_idx[o + 2] = i2A;
        g_w[o + 0] = r0 * s; g_w[o + 1] = r1 * s; g_w[o + 2] = r2 * s;
    }
    {
        float r0 = 1.0f / fmaxf(d0B, 1e-10f);
        float r1 = 1.0f / fmaxf(d1B, 1e-10f);
        float r2 = 1.0f / fmaxf(d2B, 1e-10f);
        float s = 1.0f / (r0 + r1 + r2);
        size_t o = ((size_t)b * NPTS + nB) * 3;
        g_idx[o + 0] = i0B; g_idx[o + 1] = i1B; g_idx[o + 2] = i2B;
        g_w[o + 0] = r0 * s; g_w[o + 1] = r1 * s; g_w[o + 2] = r2 * s;
    }
}

// ---------------------------------------------------------------------------
// Kernel 2: build X = concat(features1, interp(features2)), split to fp16 h/l
// ---------------------------------------------------------------------------
__global__ __launch_bounds__(384) void build_x_kernel(
    const float* __restrict__ f1, const float* __restrict__ f2)
{
    const int p = blockIdx.x;
    const int t = threadIdx.x;
    float v;

    if (t < C1DIM) {
        v = f1[(size_t)p * C1DIM + t];
    } else {
        const int c = t - C1DIM;
        const int b = p >> 14;
        const size_t o = (size_t)p * 3;
        const int i0 = g_idx[o], i1 = g_idx[o + 1], i2 = g_idx[o + 2];
        const float w0 = g_w[o], w1 = g_w[o + 1], w2 = g_w[o + 2];
        const float* base = f2 + (size_t)b * MPTS * C2DIM;
        v = w0 * base[(size_t)i0 * C2DIM + c]
          + w1 * base[(size_t)i1 * C2DIM + c]
          + w2 * base[(size_t)i2 * C2DIM + c];
    }
    __half h, l;
    split_f16(v, h, l);
    g_Xh[(size_t)p * CIN + t] = h;
    g_Xl[(size_t)p * CIN + t] = l;
}

// ---------------------------------------------------------------------------
// Kernel 2b: merged weight prep — transpose + fp16 (W3 also keeps lo part)
// W1: 98304 elems, W2: 65536, W3: 32768  -> 196608 total
// ---------------------------------------------------------------------------
__global__ void prep_w_kernel(const float* __restrict__ W1,
                              const float* __restrict__ W2,
                              const float* __restrict__ W3)
{
    int i = blockIdx.x * 256 + threadIdx.x;
    if (i < H1DIM * CIN) {
        int n = i / CIN, k = i - n * CIN;
        g_W1h[i] = __float2half_rn(W1[(size_t)k * H1DIM + n]);
    } else if (i < H1DIM * CIN + H2DIM * H1DIM) {
        int j = i - H1DIM * CIN;
        int n = j / H1DIM, k = j - n * H1DIM;
        g_W2h[j] = __float2half_rn(W2[(size_t)k * H2DIM + n]);
    } else if (i < H1DIM * CIN + H2DIM * H1DIM + COUT * H2DIM) {
        int j = i - (H1DIM * CIN + H2DIM * H1DIM);
        int n = j / H2DIM, k = j - n * H2DIM;
        __half h, l;
        split_f16(W3[(size_t)k * COUT + n], h, l);
        g_W3h[j] = h; g_W3l[j] = l;
    }
}

// ---------------------------------------------------------------------------
// Kernel 3: fp16 HMMA GEMM (mma.sync m16n8k16) with fp32 emulation.
// TWOPASS: D = Ah*Bh + Al*Bh   (B rounded to fp16; no Bl tile at all)
// 3-pass:  D = Ah*Bh + Ah*Bl + Al*Bh
// C[M,Ntot] = A[M,K] @ Bt[Ntot,K]^T + bias (opt ReLU).
// CTA 128x128, BK=32, 8 warps (4m x 2n), warp tile 32x64.
// smem row stride 80B -> conflict-free for cp.async and ldmatrix.
// ---------------------------------------------------------------------------
#define BM 128
#define BN 128
#define BK 32
#define SROW 80                       // bytes per smem row (32 fp16 + pad)
#define TILEB (128 * SROW)            // 10240 per operand tile

template <bool TWOPASS>
__device__ __forceinline__ void load_chunk(
    uint32_t sbuf,
    const __half* __restrict__ Ah, const __half* __restrict__ Al,
    const __half* __restrict__ Bh, const __half* __restrict__ Bl,
    int K, int tid)
{
    const int row = tid >> 2;         // 0..63
    const int piece = tid & 3;        // 0..3 (16B each, 64B row payload)
    const uint32_t d0 = row * SROW + piece * 16;
    const size_t g0 = (size_t)row * K + piece * 8;
    const uint32_t d1 = d0 + 64 * SROW;
    const size_t g1 = g0 + (size_t)64 * K;

    cpa16(sbuf + 0 * TILEB + d0, Ah + g0);
    cpa16(sbuf + 1 * TILEB + d0, Al + g0);
    cpa16(sbuf + 2 * TILEB + d0, Bh + g0);
    cpa16(sbuf + 0 * TILEB + d1, Ah + g1);
    cpa16(sbuf + 1 * TILEB + d1, Al + g1);
    cpa16(sbuf + 2 * TILEB + d1, Bh + g1);
    if (!TWOPASS) {
        cpa16(sbuf + 3 * TILEB + d0, Bl + g0);
        cpa16(sbuf + 3 * TILEB + d1, Bl + g1);
    }
}

template <bool TWOPASS>
__global__ __launch_bounds__(256, 2) void gemm_tc(
    const __half* __restrict__ Ah, const __half* __restrict__ Al,
    const __half* __restrict__ Bh, const __half* __restrict__ Bl,
    const float* __restrict__ bias,
    float* __restrict__ Cf,
    __half* __restrict__ Ch, __half* __restrict__ Cl,
    int K, int Ntot, int doRelu, int outHalf)
{
    constexpr uint32_t BUFB = (TWOPASS ? 3 : 4) * TILEB;
    extern __shared__ char smem[];
    const uint32_t sb = smem_to_u32(smem);
    const int tid = threadIdx.x;
    const int wid = tid >> 5;
    const int lane = tid & 31;
    const int gid = lane >> 2;        // 0..7
    const int tig = lane & 3;         // 0..3
    const int warp_m = wid >> 1;      // 0..3
    const int warp_n = wid & 1;       // 0..1
    const int m0 = blockIdx.y * BM;
    const int n0 = blockIdx.x * BN;

    const __half* Ahp = Ah + (size_t)m0 * K;
    const __half* Alp = Al + (size_t)m0 * K;
    const __half* Bhp = Bh + (size_t)n0 * K;
    const __half* Blp = TWOPASS ? nullptr : (Bl + (size_t)n0 * K);

    float acc[2][8][4];
#pragma unroll
    for (int t = 0; t < 2; t++)
#pragma unroll
        for (int nt = 0; nt < 8; nt++)
#pragma unroll
            for (int r = 0; r < 4; r++) acc[t][nt][r] = 0.0f;

    const int nch = K / BK;

    // per-lane ldmatrix address components (relative; add sA/sB + s*32)
    const uint32_t a_rel = (uint32_t)((warp_m * 32 + (lane & 15)) * SROW
                                      + ((lane >> 4) << 4));
    const uint32_t b_rel = (uint32_t)((warp_n * 64 + ((lane >> 4) << 3)
                                       + (lane & 7)) * SROW
                                      + (((lane >> 3) & 1) << 4));

    // prologue: prefetch chunks 0 and 1
    load_chunk<TWOPASS>(sb, Ahp, Alp, Bhp, Blp, K, tid);
    cpa_commit();
    if (nch > 1) {
        load_chunk<TWOPASS>(sb + BUFB, Ahp + BK, Alp + BK, Bhp + BK,
                            TWOPASS ? nullptr : (Blp + BK), K, tid);
        cpa_commit();
    }

    for (int c = 0; c < nch; c++) {
        if (c + 1 < nch) cpa_wait<1>(); else cpa_wait<0>();
        __syncthreads();

        const uint32_t sA = sb + (c & 1) * BUFB;
        const uint32_t sB = sA + 2 * TILEB;

#pragma unroll
        for (int s = 0; s < 2; s++) {             // two k16 steps per chunk
            uint32_t aF[2][2][4];
#pragma unroll
            for (int t = 0; t < 2; t++)
#pragma unroll
                for (int hl = 0; hl < 2; hl++)
                    ldsm_x4(aF[t][hl],
                            sA + hl * TILEB + a_rel + t * (16 * SROW) + s * 32);

#pragma unroll
            for (int np = 0; np < 4; np++) {      // pairs of n8 tiles
                uint32_t bh[4];
                const uint32_t ba = sB + b_rel + np * (16 * SROW) + s * 32;
                ldsm_x4(bh, ba);                  // hi: {t0 b0,b1, t1 b0,b1}
                if (TWOPASS) {
#pragma unroll
                    for (int t = 0; t < 2; t++) {
                        float* e0 = acc[t][np * 2];
                        float* e1 = acc[t][np * 2 + 1];
                        mma_f16(e0, aF[t][0], bh + 0);   // Ah*Bh
                        mma_f16(e0, aF[t][1], bh + 0);   // Al*Bh
                        mma_f16(e1, aF[t][0], bh + 2);
                        mma_f16(e1, aF[t][1], bh + 2);
                    }
                } else {
                    uint32_t bl[4];
                    ldsm_x4(bl, ba + TILEB);      // lo
#pragma unroll
                    for (int t = 0; t < 2; t++) {
                        float* e0 = acc[t][np * 2];
                        float* e1 = acc[t][np * 2 + 1];
                        mma_f16(e0, aF[t][0], bh + 0);   // Ah*Bh
                        mma_f16(e0, aF[t][0], bl + 0);   // Ah*Bl
                        mma_f16(e0, aF[t][1], bh + 0);   // Al*Bh
                        mma_f16(e1, aF[t][0], bh + 2);
                        mma_f16(e1, aF[t][0], bl + 2);
                        mma_f16(e1, aF[t][1], bh + 2);
                    }
                }
            }
        }

        __syncthreads();
        if (c + 2 < nch) {
            const int k2 = (c + 2) * BK;
            load_chunk<TWOPASS>(sb + (c & 1) * BUFB, Ahp + k2, Alp + k2,
                                Bhp + k2, TWOPASS ? nullptr : (Blp + k2),
                                K, tid);
            cpa_commit();
        }
    }

    // Epilogue: bias (+ReLU); fp32 store or fp16 hi/lo split store
#pragma unroll
    for (int t = 0; t < 2; t++) {
        const int r0 = m0 + warp_m * 32 + t * 16 + gid;
        const int r1 = r0 + 8;
#pragma unroll
        for (int nt = 0; nt < 8; nt++) {
            const int col = n0 + warp_n * 64 + nt * 8 + tig * 2;
            const float bv0 = __ldg(&bias[col]);
            const float bv1 = __ldg(&bias[col + 1]);
            float v00 = acc[t][nt][0] + bv0;
            float v01 = acc[t][nt][1] + bv1;
            float v10 = acc[t][nt][2] + bv0;
            float v11 = acc[t][nt][3] + bv1;
            if (doRelu) {
                v00 = fmaxf(v00, 0.0f); v01 = fmaxf(v01, 0.0f);
                v10 = fmaxf(v10, 0.0f); v11 = fmaxf(v11, 0.0f);
            }
            if (!outHalf) {
                *(float2*)(Cf + (size_t)r0 * Ntot + col) = make_float2(v00, v01);
                *(float2*)(Cf + (size_t)r1 * Ntot + col) = make_float2(v10, v11);
            } else {
                __half h00, l00, h01, l01, h10, l10, h11, l11;
                split_f16(v00, h00, l00); split_f16(v01, h01, l01);
                split_f16(v10, h10, l10); split_f16(v11, h11, l11);
                *(__half2*)(Ch + (size_t)r0 * Ntot + col) = __halves2half2(h00, h01);
                *(__half2*)(Cl + (size_t)r0 * Ntot + col) = __halves2half2(l00, l01);
                *(__half2*)(Ch + (size_t)r1 * Ntot + col) = __halves2half2(h10, h11);
                *(__half2*)(Cl + (size_t)r1 * Ntot + col) = __halves2half2(l10, l11);
            }
        }
    }
}

// ---------------------------------------------------------------------------
// Launch
// ---------------------------------------------------------------------------
extern "C" void kernel_launch(void* const* d_in, const int* in_sizes, int n_in,
                              void* d_out, int out_size)
{
    const float* xyz1 = (const float*)d_in[0];
    const float* xyz2 = (const float*)d_in[1];
    const float* f1   = (const float*)d_in[2];
    const float* f2   = (const float*)d_in[3];
    const float* W1   = (const float*)d_in[4];
    const float* b1   = (const float*)d_in[5];
    const float* W2   = (const float*)d_in[6];
    const float* b2   = (const float*)d_in[7];
    const float* W3   = (const float*)d_in[8];
    const float* b3   = (const float*)d_in[9];
    float* out = (float*)d_out;

    void *xh, *xl, *hah, *hal, *hbh, *hbl, *w1h, *w2h, *w3h, *w3l;
    cudaGetSymbolAddress(&xh,  g_Xh);  cudaGetSymbolAddress(&xl,  g_Xl);
    cudaGetSymbolAddress(&hah, g_Hah); cudaGetSymbolAddress(&hal, g_Hal);
    cudaGetSymbolAddress(&hbh, g_Hbh); cudaGetSymbolAddress(&hbl, g_Hbl);
    cudaGetSymbolAddress(&w1h, g_W1h); cudaGetSymbolAddress(&w2h, g_W2h);
    cudaGetSymbolAddress(&w3h, g_W3h); cudaGetSymbolAddress(&w3l, g_W3l);

    __half *Xh=(__half*)xh, *Xl=(__half*)xl;
    __half *Hah=(__half*)hah, *Hal=(__half*)hal;
    __half *Hbh=(__half*)hbh, *Hbl=(__half*)hbl;
    __half *W1h=(__half*)w1h, *W2h=(__half*)w2h;
    __half *W3h=(__half*)w3h, *W3l=(__half*)w3l;

    const int smem2 = 2 * 3 * TILEB;   // 61440
    const int smem3 = 2 * 4 * TILEB;   // 81920
    cudaFuncSetAttribute(gemm_tc<true>,
                         cudaFuncAttributeMaxDynamicSharedMemorySize, smem2);
    cudaFuncSetAttribute(gemm_tc<false>,
                         cudaFuncAttributeMaxDynamicSharedMemorySize, smem3);

    dim3 g1(NPTS / 512, BATCH);
    three_nn_kernel<<<g1, 256>>>(xyz1, xyz2);

    build_x_kernel<<<TOTAL, 384>>>(f1, f2);

    const int prep_total = H1DIM * CIN + H2DIM * H1DIM + COUT * H2DIM;
    prep_w_kernel<<<(prep_total + 255) / 256, 256>>>(W1, W2, W3);

    gemm_tc<true><<<dim3(H1DIM / BN, TOTAL / BM), 256, smem2>>>(
        Xh, Xl, W1h, nullptr, b1, nullptr, Hah, Hal, CIN, H1DIM, 1, 1);
    gemm_tc<true><<<dim3(H2DIM / BN, TOTAL / BM), 256, smem2>>>(
        Hah, Hal, W2h, nullptr, b2, nullptr, Hbh, Hbl, H1DIM, H2DIM, 1, 1);
    gemm_tc<false><<<dim3(COUT / BN, TOTAL / BM), 256, smem3>>>(
        Hbh, Hbl, W3h, W3l, b3, out, nullptr, nullptr, H2DIM, COUT, 0, 0);
}

// round 9
// speedup vs baseline: 1.3301x; 1.3301x over previous
#include <cuda_runtime.h>
#include <cuda_fp16.h>
#include <cstdint>

// Problem constants (fixed shapes for this dataset)
#define BATCH   4
#define NPTS    16384
#define MPTS    4096
#define C1DIM   128
#define C2DIM   256
#define CIN     384       // C1 + C2
#define H1DIM   256
#define H2DIM   256
#define COUT    128
#define TOTAL   (BATCH * NPTS)   // 65536 points

// ---------------------------------------------------------------------------
// Scratch (static device globals — no runtime allocation allowed)
// ---------------------------------------------------------------------------
__device__ int   g_idx[TOTAL * 3];
__device__ float g_w[TOTAL * 3];
__device__ __align__(256) __half g_Xh[(size_t)TOTAL * CIN];
__device__ __align__(256) __half g_Hah[(size_t)TOTAL * H1DIM];
__device__ __align__(256) __half g_Hbh[(size_t)TOTAL * H2DIM];
__device__ __align__(256) __half g_Hbl[(size_t)TOTAL * H2DIM];
__device__ __align__(256) __half g_W1h[H1DIM * CIN];
__device__ __align__(256) __half g_W2h[H2DIM * H1DIM];
__device__ __align__(256) __half g_W3h[COUT * H2DIM];
__device__ __align__(256) __half g_W3l[COUT * H2DIM];

// ---------------------------------------------------------------------------
// Small helpers
// ---------------------------------------------------------------------------
__device__ __forceinline__ uint32_t smem_to_u32(const void* p) {
    uint32_t a;
    asm("{ .reg .u64 t; cvta.to.shared.u64 t, %1; cvt.u32.u64 %0, t; }"
        : "=r"(a) : "l"(p));
    return a;
}
__device__ __forceinline__ void cpa16(uint32_t dst, const void* src) {
    asm volatile("cp.async.cg.shared.global [%0], [%1], 16;"
                 :: "r"(dst), "l"(src));
}
__device__ __forceinline__ void cpa_commit() {
    asm volatile("cp.async.commit_group;" ::: "memory");
}
template <int N>
__device__ __forceinline__ void cpa_wait() {
    asm volatile("cp.async.wait_group %0;" :: "n"(N) : "memory");
}
__device__ __forceinline__ void ldsm_x4(uint32_t* r, uint32_t addr) {
    asm volatile("ldmatrix.sync.aligned.m8n8.x4.shared.b16 {%0,%1,%2,%3}, [%4];"
                 : "=r"(r[0]), "=r"(r[1]), "=r"(r[2]), "=r"(r[3]) : "r"(addr));
}
// m16n8k16 row.col fp16 MMA, f32 accumulate
__device__ __forceinline__ void mma_f16(float* d, const uint32_t* a,
                                        const uint32_t* b) {
    asm("mma.sync.aligned.m16n8k16.row.col.f32.f16.f16.f32 "
        "{%0,%1,%2,%3}, {%4,%5,%6,%7}, {%8,%9}, {%0,%1,%2,%3};"
        : "+f"(d[0]), "+f"(d[1]), "+f"(d[2]), "+f"(d[3])
        : "r"(a[0]), "r"(a[1]), "r"(a[2]), "r"(a[3]), "r"(b[0]), "r"(b[1]));
}
// fp32 -> fp16 hi/lo split
__device__ __forceinline__ void split_f16(float x, __half& h, __half& l) {
    h = __float2half_rn(x);
    l = __float2half_rn(x - __half2float(h));
}
// packed f32x2 helpers (sm_100+; proven on this harness)
__device__ __forceinline__ unsigned long long pk2(float a, float b) {
    unsigned long long r;
    asm("mov.b64 %0, {%1, %2};" : "=l"(r)
        : "r"(__float_as_uint(a)), "r"(__float_as_uint(b)));
    return r;
}
__device__ __forceinline__ unsigned long long add2(unsigned long long a,
                                                   unsigned long long b) {
    unsigned long long r;
    asm("add.rn.f32x2 %0, %1, %2;" : "=l"(r) : "l"(a), "l"(b));
    return r;
}
__device__ __forceinline__ unsigned long long mul2(unsigned long long a,
                                                   unsigned long long b) {
    unsigned long long r;
    asm("mul.rn.f32x2 %0, %1, %2;" : "=l"(r) : "l"(a), "l"(b));
    return r;
}
__device__ __forceinline__ unsigned long long fma2(unsigned long long a,
                                                   unsigned long long b,
                                                   unsigned long long c) {
    unsigned long long r;
    asm("fma.rn.f32x2 %0, %1, %2, %3;" : "=l"(r) : "l"(a), "l"(b), "l"(c));
    return r;
}
__device__ __forceinline__ void unpk2(unsigned long long v, float& lo, float& hi) {
    uint32_t a, b;
    asm("mov.b64 {%0, %1}, %2;" : "=r"(a), "=r"(b) : "l"(v));
    lo = __uint_as_float(a);
    hi = __uint_as_float(b);
}

// ---------------------------------------------------------------------------
// Kernel 1: three_nn + interpolation weights (R7 config: 1 point per thread)
// ---------------------------------------------------------------------------
__device__ __forceinline__ void upd3(float d, int j,
                                     float& d0, float& d1, float& d2,
                                     int& i0, int& i1, int& i2) {
    if (d < d2) {
        if (d < d1) {
            d2 = d1; i2 = i1;
            if (d < d0) { d1 = d0; i1 = i0; d0 = d; i0 = j; }
            else        { d1 = d;  i1 = j; }
        } else {
            d2 = d; i2 = j;
        }
    }
}

__global__ __launch_bounds__(256) void three_nn_kernel(
    const float* __restrict__ xyz1, const float* __restrict__ xyz2)
{
    // negated xyz2 coords, accessed as packed float pairs
    __shared__ __align__(8) float snx[MPTS];
    __shared__ __align__(8) float sny[MPTS];
    __shared__ __align__(8) float snz[MPTS];

    const int b = blockIdx.y;
    const float* p2 = xyz2 + (size_t)b * MPTS * 3;
    for (int j = threadIdx.x; j < MPTS; j += 256) {
        snx[j] = -p2[3 * j + 0];
        sny[j] = -p2[3 * j + 1];
        snz[j] = -p2[3 * j + 2];
    }
    __syncthreads();

    const int n = blockIdx.x * 256 + threadIdx.x;
    const float* p1 = xyz1 + ((size_t)b * NPTS + n) * 3;
    const float x = p1[0], y = p1[1], z = p1[2];
    const unsigned long long x2 = pk2(x, x);
    const unsigned long long y2 = pk2(y, y);
    const unsigned long long z2 = pk2(z, z);

    float d0 = 1e30f, d1 = 1e30f, d2 = 1e30f;
    int   i0 = 0, i1 = 0, i2 = 0;

    const unsigned long long* nxp = (const unsigned long long*)snx;
    const unsigned long long* nyp = (const unsigned long long*)sny;
    const unsigned long long* nzp = (const unsigned long long*)snz;

#pragma unroll 4
    for (int p = 0; p < MPTS / 2; p++) {
        unsigned long long dx = add2(x2, nxp[p]);
        unsigned long long dy = add2(y2, nyp[p]);
        unsigned long long dz = add2(z2, nzp[p]);
        unsigned long long dd = mul2(dx, dx);
        dd = fma2(dy, dy, dd);
        dd = fma2(dz, dz, dd);
        float lo, hi;
        unpk2(dd, lo, hi);
        if (fminf(lo, hi) < d2) {
            upd3(lo, 2 * p,     d0, d1, d2, i0, i1, i2);
            upd3(hi, 2 * p + 1, d0, d1, d2, i0, i1, i2);
        }
    }

    float r0 = 1.0f / fmaxf(d0, 1e-10f);
    float r1 = 1.0f / fmaxf(d1, 1e-10f);
    float r2 = 1.0f / fmaxf(d2, 1e-10f);
    float s = 1.0f / (r0 + r1 + r2);

    size_t o = ((size_t)b * NPTS + n) * 3;
    g_idx[o + 0] = i0; g_idx[o + 1] = i1; g_idx[o + 2] = i2;
    g_w[o + 0] = r0 * s; g_w[o + 1] = r1 * s; g_w[o + 2] = r2 * s;
}

// ---------------------------------------------------------------------------
// Kernel 2: build X = concat(features1, interp(features2)) -> fp16
// ---------------------------------------------------------------------------
__global__ __launch_bounds__(384) void build_x_kernel(
    const float* __restrict__ f1, const float* __restrict__ f2)
{
    const int p = blockIdx.x;
    const int t = threadIdx.x;
    float v;

    if (t < C1DIM) {
        v = f1[(size_t)p * C1DIM + t];
    } else {
        const int c = t - C1DIM;
        const int b = p >> 14;
        const size_t o = (size_t)p * 3;
        const int i0 = g_idx[o], i1 = g_idx[o + 1], i2 = g_idx[o + 2];
        const float w0 = g_w[o], w1 = g_w[o + 1], w2 = g_w[o + 2];
        const float* base = f2 + (size_t)b * MPTS * C2DIM;
        v = w0 * base[(size_t)i0 * C2DIM + c]
          + w1 * base[(size_t)i1 * C2DIM + c]
          + w2 * base[(size_t)i2 * C2DIM + c];
    }
    g_Xh[(size_t)p * CIN + t] = __float2half_rn(v);
}

// ---------------------------------------------------------------------------
// Kernel 2b: merged weight prep — transpose + fp16 (W3 keeps lo part)
// ---------------------------------------------------------------------------
__global__ void prep_w_kernel(const float* __restrict__ W1,
                              const float* __restrict__ W2,
                              const float* __restrict__ W3)
{
    int i = blockIdx.x * 256 + threadIdx.x;
    if (i < H1DIM * CIN) {
        int n = i / CIN, k = i - n * CIN;
        g_W1h[i] = __float2half_rn(W1[(size_t)k * H1DIM + n]);
    } else if (i < H1DIM * CIN + H2DIM * H1DIM) {
        int j = i - H1DIM * CIN;
        int n = j / H1DIM, k = j - n * H1DIM;
        g_W2h[j] = __float2half_rn(W2[(size_t)k * H2DIM + n]);
    } else if (i < H1DIM * CIN + H2DIM * H1DIM + COUT * H2DIM) {
        int j = i - (H1DIM * CIN + H2DIM * H1DIM);
        int n = j / H2DIM, k = j - n * H2DIM;
        __half h, l;
        split_f16(W3[(size_t)k * COUT + n], h, l);
        g_W3h[j] = h; g_W3l[j] = l;
    }
}

// ---------------------------------------------------------------------------
// GEMM common geometry: CTA 128x128, BK=32, 8 warps (4m x 2n), warp 32x64.
// smem row stride 80B -> conflict-free for cp.async and ldmatrix.
// ---------------------------------------------------------------------------
#define BM 128
#define BN 128
#define BK 32
#define SROW 80
#define TILEB (128 * SROW)            // 10240 per operand tile

// ---------------------------------------------------------------------------
// Kernel 3a: SINGLE-PASS fp16 GEMM, 3-stage cp.async ring, 1 sync per chunk.
// C[M,Ntot] = A[M,K] @ B[Ntot,K]^T + bias (opt ReLU).
// outMode: 1 = fp16 h/l split store, 2 = fp16 h-only store.
// ---------------------------------------------------------------------------
#define SBUF (2 * TILEB)              // per stage: A tile then B tile
#define SP_SMEM (3 * SBUF)            // 61440

__device__ __forceinline__ void load2(uint32_t sbuf,
                                      const __half* __restrict__ A,
                                      const __half* __restrict__ B,
                                      int K, int tid)
{
    const int row = tid >> 2;
    const int piece = tid & 3;
    const uint32_t d0 = row * SROW + piece * 16;
    const size_t g0 = (size_t)row * K + piece * 8;
    const uint32_t d1 = d0 + 64 * SROW;
    const size_t g1 = g0 + (size_t)64 * K;
    cpa16(sbuf + d0, A + g0);
    cpa16(sbuf + d1, A + g1);
    cpa16(sbuf + TILEB + d0, B + g0);
    cpa16(sbuf + TILEB + d1, B + g1);
}

__global__ __launch_bounds__(256, 2) void gemm_sp(
    const __half* __restrict__ A, const __half* __restrict__ B,
    const float* __restrict__ bias,
    __half* __restrict__ Ch, __half* __restrict__ Cl,
    int K, int Ntot, int doRelu, int outMode)
{
    extern __shared__ char smem[];
    const uint32_t sb = smem_to_u32(smem);
    const int tid = threadIdx.x;
    const int wid = tid >> 5;
    const int lane = tid & 31;
    const int gid = lane >> 2;
    const int tig = lane & 3;
    const int warp_m = wid >> 1;
    const int warp_n = wid & 1;
    const int m0 = blockIdx.y * BM;
    const int n0 = blockIdx.x * BN;

    const __half* Ap = A + (size_t)m0 * K;
    const __half* Bp = B + (size_t)n0 * K;

    float acc[2][8][4];
#pragma unroll
    for (int t = 0; t < 2; t++)
#pragma unroll
        for (int nt = 0; nt < 8; nt++)
#pragma unroll
            for (int r = 0; r < 4; r++) acc[t][nt][r] = 0.0f;

    const int nch = K / BK;

    const uint32_t a_rel = (uint32_t)((warp_m * 32 + (lane & 15)) * SROW
                                      + ((lane >> 4) << 4));
    const uint32_t b_rel = (uint32_t)((warp_n * 64 + ((lane >> 4) << 3)
                                       + (lane & 7)) * SROW
                                      + (((lane >> 3) & 1) << 4));

    // prologue: stages for chunks 0, 1
    load2(sb + 0 * SBUF, Ap, Bp, K, tid);
    cpa_commit();
    load2(sb + 1 * SBUF, Ap + BK, Bp + BK, K, tid);
    cpa_commit();

    int stg = 2;                       // stage slot for chunk c+2
    for (int c = 0; c < nch; c++) {
        cpa_wait<1>();                 // chunk c data complete (own copies)
        __syncthreads();               // all warps: data visible, prev compute done

        // issue chunk c+2 into the stage consumed at c-1 (safe after barrier)
        if (c + 2 < nch)
            load2(sb + stg * SBUF, Ap + (c + 2) * BK, Bp + (c + 2) * BK, K, tid);
        cpa_commit();                  // always commit to keep group accounting
        stg = (stg + 1 == 3) ? 0 : stg + 1;

        const uint32_t sA = sb + (c % 3) * SBUF;
        const uint32_t sB = sA + TILEB;

#pragma unroll
        for (int s = 0; s < 2; s++) {
            uint32_t aF[2][4];
#pragma unroll
            for (int t = 0; t < 2; t++)
                ldsm_x4(aF[t], sA + a_rel + t * (16 * SROW) + s * 32);
#pragma unroll
            for (int np = 0; np < 4; np++) {
                uint32_t bh[4];
                ldsm_x4(bh, sB + b_rel + np * (16 * SROW) + s * 32);
#pragma unroll
                for (int t = 0; t < 2; t++) {
                    mma_f16(acc[t][np * 2],     aF[t], bh + 0);
                    mma_f16(acc[t][np * 2 + 1], aF[t], bh + 2);
                }
            }
        }
    }

    // Epilogue
#pragma unroll
    for (int t = 0; t < 2; t++) {
        const int r0 = m0 + warp_m * 32 + t * 16 + gid;
        const int r1 = r0 + 8;
#pragma unroll
        for (int nt = 0; nt < 8; nt++) {
            const int col = n0 + warp_n * 64 + nt * 8 + tig * 2;
            const float bv0 = __ldg(&bias[col]);
            const float bv1 = __ldg(&bias[col + 1]);
            float v00 = acc[t][nt][0] + bv0;
            float v01 = acc[t][nt][1] + bv1;
            float v10 = acc[t][nt][2] + bv0;
            float v11 = acc[t][nt][3] + bv1;
            if (doRelu) {
                v00 = fmaxf(v00, 0.0f); v01 = fmaxf(v01, 0.0f);
                v10 = fmaxf(v10, 0.0f); v11 = fmaxf(v11, 0.0f);
            }
            if (outMode == 2) {
                *(__half2*)(Ch + (size_t)r0 * Ntot + col) =
                    __halves2half2(__float2half_rn(v00), __float2half_rn(v01));
                *(__half2*)(Ch + (size_t)r1 * Ntot + col) =
                    __halves2half2(__float2half_rn(v10), __float2half_rn(v11));
            } else {
                __half h00, l00, h01, l01, h10, l10, h11, l11;
                split_f16(v00, h00, l00); split_f16(v01, h01, l01);
                split_f16(v10, h10, l10); split_f16(v11, h11, l11);
                *(__half2*)(Ch + (size_t)r0 * Ntot + col) = __halves2half2(h00, h01);
                *(__half2*)(Cl + (size_t)r0 * Ntot + col) = __halves2half2(l00, l01);
                *(__half2*)(Ch + (size_t)r1 * Ntot + col) = __halves2half2(h10, h11);
                *(__half2*)(Cl + (size_t)r1 * Ntot + col) = __halves2half2(l10, l11);
            }
        }
    }
}

// ---------------------------------------------------------------------------
// Kernel 3b: 3-pass fp16 GEMM (final layer; A split h/l, B split h/l),
// 2-stage double buffer (proven R8 structure). fp32 output.
// ---------------------------------------------------------------------------
#define BUF3 (4 * TILEB)
#define TP_SMEM (2 * BUF3)            // 81920

__device__ __forceinline__ void load4(uint32_t sbuf,
                                      const __half* __restrict__ Ah,
                                      const __half* __restrict__ Al,
                                      const __half* __restrict__ Bh,
                                      const __half* __restrict__ Bl,
                                      int K, int tid)
{
    const int row = tid >> 2;
    const int piece = tid & 3;
    const uint32_t d0 = row * SROW + piece * 16;
    const size_t g0 = (size_t)row * K + piece * 8;
    const uint32_t d1 = d0 + 64 * SROW;
    const size_t g1 = g0 + (size_t)64 * K;

    cpa16(sbuf + 0 * TILEB + d0, Ah + g0);
    cpa16(sbuf + 1 * TILEB + d0, Al + g0);
    cpa16(sbuf + 2 * TILEB + d0, Bh + g0);
    cpa16(sbuf + 3 * TILEB + d0, Bl + g0);
    cpa16(sbuf + 0 * TILEB + d1, Ah + g1);
    cpa16(sbuf + 1 * TILEB + d1, Al + g1);
    cpa16(sbuf + 2 * TILEB + d1, Bh + g1);
    cpa16(sbuf + 3 * TILEB + d1, Bl + g1);
}

__global__ __launch_bounds__(256, 2) void gemm_3p(
    const __half* __restrict__ Ah, const __half* __restrict__ Al,
    const __half* __restrict__ Bh, const __half* __restrict__ Bl,
    const float* __restrict__ bias, float* __restrict__ Cf,
    int K, int Ntot)
{
    extern __shared__ char smem[];
    const uint32_t sb = smem_to_u32(smem);
    const int tid = threadIdx.x;
    const int wid = tid >> 5;
    const int lane = tid & 31;
    const int gid = lane >> 2;
    const int tig = lane & 3;
    const int warp_m = wid >> 1;
    const int warp_n = wid & 1;
    const int m0 = blockIdx.y * BM;
    const int n0 = blockIdx.x * BN;

    const __half* Ahp = Ah + (size_t)m0 * K;
    const __half* Alp = Al + (size_t)m0 * K;
    const __half* Bhp = Bh + (size_t)n0 * K;
    const __half* Blp = Bl + (size_t)n0 * K;

    float acc[2][8][4];
#pragma unroll
    for (int t = 0; t < 2; t++)
#pragma unroll
        for (int nt = 0; nt < 8; nt++)
#pragma unroll
            for (int r = 0; r < 4; r++) acc[t][nt][r] = 0.0f;

    const int nch = K / BK;

    const uint32_t a_rel = (uint32_t)((warp_m * 32 + (lane & 15)) * SROW
                                      + ((lane >> 4) << 4));
    const uint32_t b_rel = (uint32_t)((warp_n * 64 + ((lane >> 4) << 3)
                                       + (lane & 7)) * SROW
                                      + (((lane >> 3) & 1) << 4));

    load4(sb, Ahp, Alp, Bhp, Blp, K, tid);
    cpa_commit();
    if (nch > 1) {
        load4(sb + BUF3, Ahp + BK, Alp + BK, Bhp + BK, Blp + BK, K, tid);
        cpa_commit();
    }

    for (int c = 0; c < nch; c++) {
        if (c + 1 < nch) cpa_wait<1>(); else cpa_wait<0>();
        __syncthreads();

        const uint32_t sA = sb + (c & 1) * BUF3;
        const uint32_t sB = sA + 2 * TILEB;

#pragma unroll
        for (int s = 0; s < 2; s++) {
            uint32_t aF[2][2][4];
#pragma unroll
            for (int t = 0; t < 2; t++)
#pragma unroll
                for (int hl = 0; hl < 2; hl++)
                    ldsm_x4(aF[t][hl],
                            sA + hl * TILEB + a_rel + t * (16 * SROW) + s * 32);

#pragma unroll
            for (int np = 0; np < 4; np++) {
                uint32_t bh[4], bl[4];
                const uint32_t ba = sB + b_rel + np * (16 * SROW) + s * 32;
                ldsm_x4(bh, ba);
                ldsm_x4(bl, ba + TILEB);
#pragma unroll
                for (int t = 0; t < 2; t++) {
                    float* e0 = acc[t][np * 2];
                    float* e1 = acc[t][np * 2 + 1];
                    mma_f16(e0, aF[t][0], bh + 0);
                    mma_f16(e0, aF[t][0], bl + 0);
                    mma_f16(e0, aF[t][1], bh + 0);
                    mma_f16(e1, aF[t][0], bh + 2);
                    mma_f16(e1, aF[t][0], bl + 2);
                    mma_f16(e1, aF[t][1], bh + 2);
                }
            }
        }

        __syncthreads();
        if (c + 2 < nch) {
            const int k2 = (c + 2) * BK;
            load4(sb + (c & 1) * BUF3, Ahp + k2, Alp + k2, Bhp + k2, Blp + k2,
                  K, tid);
            cpa_commit();
        }
    }

#pragma unroll
    for (int t = 0; t < 2; t++) {
        const int r0 = m0 + warp_m * 32 + t * 16 + gid;
        const int r1 = r0 + 8;
#pragma unroll
        for (int nt = 0; nt < 8; nt++) {
            const int col = n0 + warp_n * 64 + nt * 8 + tig * 2;
            const float bv0 = __ldg(&bias[col]);
            const float bv1 = __ldg(&bias[col + 1]);
            *(float2*)(Cf + (size_t)r0 * Ntot + col) =
                make_float2(acc[t][nt][0] + bv0, acc[t][nt][1] + bv1);
            *(float2*)(Cf + (size_t)r1 * Ntot + col) =
                make_float2(acc[t][nt][2] + bv0, acc[t][nt][3] + bv1);
        }
    }
}

// ---------------------------------------------------------------------------
// Launch
// ---------------------------------------------------------------------------
extern "C" void kernel_launch(void* const* d_in, const int* in_sizes, int n_in,
                              void* d_out, int out_size)
{
    const float* xyz1 = (const float*)d_in[0];
    const float* xyz2 = (const float*)d_in[1];
    const float* f1   = (const float*)d_in[2];
    const float* f2   = (const float*)d_in[3];
    const float* W1   = (const float*)d_in[4];
    const float* b1   = (const float*)d_in[5];
    const float* W2   = (const float*)d_in[6];
    const float* b2   = (const float*)d_in[7];
    const float* W3   = (const float*)d_in[8];
    const float* b3   = (const float*)d_in[9];
    float* out = (float*)d_out;

    void *xh, *hah, *hbh, *hbl, *w1h, *w2h, *w3h, *w3l;
    cudaGetSymbolAddress(&xh,  g_Xh);
    cudaGetSymbolAddress(&hah, g_Hah);
    cudaGetSymbolAddress(&hbh, g_Hbh); cudaGetSymbolAddress(&hbl, g_Hbl);
    cudaGetSymbolAddress(&w1h, g_W1h); cudaGetSymbolAddress(&w2h, g_W2h);
    cudaGetSymbolAddress(&w3h, g_W3h); cudaGetSymbolAddress(&w3l, g_W3l);

    __half *Xh=(__half*)xh, *Hah=(__half*)hah;
    __half *Hbh=(__half*)hbh, *Hbl=(__half*)hbl;
    __half *W1h=(__half*)w1h, *W2h=(__half*)w2h;
    __half *W3h=(__half*)w3h, *W3l=(__half*)w3l;

    cudaFuncSetAttribute(gemm_sp,
                         cudaFuncAttributeMaxDynamicSharedMemorySize, SP_SMEM);
    cudaFuncSetAttribute(gemm_3p,
                         cudaFuncAttributeMaxDynamicSharedMemorySize, TP_SMEM);

    dim3 g1(NPTS / 256, BATCH);
    three_nn_kernel<<<g1, 256>>>(xyz1, xyz2);

    build_x_kernel<<<TOTAL, 384>>>(f1, f2);

    const int prep_total = H1DIM * CIN + H2DIM * H1DIM + COUT * H2DIM;
    prep_w_kernel<<<(prep_total + 255) / 256, 256>>>(W1, W2, W3);

    gemm_sp<<<dim3(H1DIM / BN, TOTAL / BM), 256, SP_SMEM>>>(
        Xh, W1h, b1, Hah, nullptr, CIN, H1DIM, 1, 2);
    gemm_sp<<<dim3(H2DIM / BN, TOTAL / BM), 256, SP_SMEM>>>(
        Hah, W2h, b2, Hbh, Hbl, H1DIM, H2DIM, 1, 1);
    gemm_3p<<<dim3(COUT / BN, TOTAL / BM), 256, TP_SMEM>>>(
        Hbh, Hbl, W3h, W3l, b3, out, H2DIM, COUT);
}

// round 10
// speedup vs baseline: 1.6021x; 1.2045x over previous
#include <cuda_runtime.h>
#include <cuda_fp16.h>
#include <cstdint>

// Problem constants (fixed shapes for this dataset)
#define BATCH   4
#define NPTS    16384
#define MPTS    4096
#define C1DIM   128
#define C2DIM   256
#define CIN     384       // C1 + C2
#define H1DIM   256
#define H2DIM   256
#define COUT    128
#define TOTAL   (BATCH * NPTS)   // 65536 points

// ---------------------------------------------------------------------------
// Scratch (static device globals — no runtime allocation allowed)
// ---------------------------------------------------------------------------
__device__ int   g_idx[TOTAL * 3];
__device__ float g_w[TOTAL * 3];
__device__ __align__(256) __half g_Xh[(size_t)TOTAL * CIN];
__device__ __align__(256) __half g_Hah[(size_t)TOTAL * H1DIM];
__device__ __align__(256) __half g_Hbh[(size_t)TOTAL * H2DIM];
__device__ __align__(256) __half g_W1h[H1DIM * CIN];
__device__ __align__(256) __half g_W2h[H2DIM * H1DIM];
__device__ __align__(256) __half g_W3h[COUT * H2DIM];

// ---------------------------------------------------------------------------
// Small helpers
// ---------------------------------------------------------------------------
__device__ __forceinline__ uint32_t smem_to_u32(const void* p) {
    uint32_t a;
    asm("{ .reg .u64 t; cvta.to.shared.u64 t, %1; cvt.u32.u64 %0, t; }"
        : "=r"(a) : "l"(p));
    return a;
}
__device__ __forceinline__ void cpa16(uint32_t dst, const void* src) {
    asm volatile("cp.async.cg.shared.global [%0], [%1], 16;"
                 :: "r"(dst), "l"(src));
}
__device__ __forceinline__ void cpa_commit() {
    asm volatile("cp.async.commit_group;" ::: "memory");
}
template <int N>
__device__ __forceinline__ void cpa_wait() {
    asm volatile("cp.async.wait_group %0;" :: "n"(N) : "memory");
}
__device__ __forceinline__ void ldsm_x4(uint32_t* r, uint32_t addr) {
    asm volatile("ldmatrix.sync.aligned.m8n8.x4.shared.b16 {%0,%1,%2,%3}, [%4];"
                 : "=r"(r[0]), "=r"(r[1]), "=r"(r[2]), "=r"(r[3]) : "r"(addr));
}
// m16n8k16 row.col fp16 MMA, f32 accumulate
__device__ __forceinline__ void mma_f16(float* d, const uint32_t* a,
                                        const uint32_t* b) {
    asm("mma.sync.aligned.m16n8k16.row.col.f32.f16.f16.f32 "
        "{%0,%1,%2,%3}, {%4,%5,%6,%7}, {%8,%9}, {%0,%1,%2,%3};"
        : "+f"(d[0]), "+f"(d[1]), "+f"(d[2]), "+f"(d[3])
        : "r"(a[0]), "r"(a[1]), "r"(a[2]), "r"(a[3]), "r"(b[0]), "r"(b[1]));
}
// packed f32x2 helpers (sm_100+; proven on this harness)
__device__ __forceinline__ unsigned long long pk2(float a, float b) {
    unsigned long long r;
    asm("mov.b64 %0, {%1, %2};" : "=l"(r)
        : "r"(__float_as_uint(a)), "r"(__float_as_uint(b)));
    return r;
}
__device__ __forceinline__ unsigned long long add2(unsigned long long a,
                                                   unsigned long long b) {
    unsigned long long r;
    asm("add.rn.f32x2 %0, %1, %2;" : "=l"(r) : "l"(a), "l"(b));
    return r;
}
__device__ __forceinline__ unsigned long long mul2(unsigned long long a,
                                                   unsigned long long b) {
    unsigned long long r;
    asm("mul.rn.f32x2 %0, %1, %2;" : "=l"(r) : "l"(a), "l"(b));
    return r;
}
__device__ __forceinline__ unsigned long long fma2(unsigned long long a,
                                                   unsigned long long b,
                                                   unsigned long long c) {
    unsigned long long r;
    asm("fma.rn.f32x2 %0, %1, %2, %3;" : "=l"(r) : "l"(a), "l"(b), "l"(c));
    return r;
}
__device__ __forceinline__ void unpk2(unsigned long long v, float& lo, float& hi) {
    uint32_t a, b;
    asm("mov.b64 {%0, %1}, %2;" : "=r"(a), "=r"(b) : "l"(v));
    lo = __uint_as_float(a);
    hi = __uint_as_float(b);
}

// ---------------------------------------------------------------------------
// Kernel 1: three_nn + interpolation weights. 4 candidates per iteration.
// ---------------------------------------------------------------------------
__device__ __forceinline__ void upd3(float d, int j,
                                     float& d0, float& d1, float& d2,
                                     int& i0, int& i1, int& i2) {
    if (d < d2) {
        if (d < d1) {
            d2 = d1; i2 = i1;
            if (d < d0) { d1 = d0; i1 = i0; d0 = d; i0 = j; }
            else        { d1 = d;  i1 = j; }
        } else {
            d2 = d; i2 = j;
        }
    }
}

__global__ __launch_bounds__(256) void three_nn_kernel(
    const float* __restrict__ xyz1, const float* __restrict__ xyz2)
{
    // negated xyz2 coords, accessed as packed float quads
    __shared__ __align__(16) float snx[MPTS];
    __shared__ __align__(16) float sny[MPTS];
    __shared__ __align__(16) float snz[MPTS];

    const int b = blockIdx.y;
    const float* p2 = xyz2 + (size_t)b * MPTS * 3;
    for (int j = threadIdx.x; j < MPTS; j += 256) {
        snx[j] = -p2[3 * j + 0];
        sny[j] = -p2[3 * j + 1];
        snz[j] = -p2[3 * j + 2];
    }
    __syncthreads();

    const int n = blockIdx.x * 256 + threadIdx.x;
    const float* p1 = xyz1 + ((size_t)b * NPTS + n) * 3;
    const float x = p1[0], y = p1[1], z = p1[2];
    const unsigned long long x2 = pk2(x, x);
    const unsigned long long y2 = pk2(y, y);
    const unsigned long long z2 = pk2(z, z);

    float d0 = 1e30f, d1 = 1e30f, d2 = 1e30f;
    int   i0 = 0, i1 = 0, i2 = 0;

    const ulonglong2* nxp = (const ulonglong2*)snx;
    const ulonglong2* nyp = (const ulonglong2*)sny;
    const ulonglong2* nzp = (const ulonglong2*)snz;

#pragma unroll 2
    for (int p = 0; p < MPTS / 4; p++) {
        const ulonglong2 cx = nxp[p];
        const ulonglong2 cy = nyp[p];
        const ulonglong2 cz = nzp[p];
        unsigned long long dx0 = add2(x2, cx.x);
        unsigned long long dy0 = add2(y2, cy.x);
        unsigned long long dz0 = add2(z2, cz.x);
        unsigned long long dd0 = mul2(dx0, dx0);
        dd0 = fma2(dy0, dy0, dd0);
        dd0 = fma2(dz0, dz0, dd0);
        unsigned long long dx1 = add2(x2, cx.y);
        unsigned long long dy1 = add2(y2, cy.y);
        unsigned long long dz1 = add2(z2, cz.y);
        unsigned long long dd1 = mul2(dx1, dx1);
        dd1 = fma2(dy1, dy1, dd1);
        dd1 = fma2(dz1, dz1, dd1);
        float l0, h0, l1, h1;
        unpk2(dd0, l0, h0);
        unpk2(dd1, l1, h1);
        const float m = fminf(fminf(l0, h0), fminf(l1, h1));
        if (m < d2) {
            upd3(l0, 4 * p,     d0, d1, d2, i0, i1, i2);
            upd3(h0, 4 * p + 1, d0, d1, d2, i0, i1, i2);
            upd3(l1, 4 * p + 2, d0, d1, d2, i0, i1, i2);
            upd3(h1, 4 * p + 3, d0, d1, d2, i0, i1, i2);
        }
    }

    float r0 = 1.0f / fmaxf(d0, 1e-10f);
    float r1 = 1.0f / fmaxf(d1, 1e-10f);
    float r2 = 1.0f / fmaxf(d2, 1e-10f);
    float s = 1.0f / (r0 + r1 + r2);

    size_t o = ((size_t)b * NPTS + n) * 3;
    g_idx[o + 0] = i0; g_idx[o + 1] = i1; g_idx[o + 2] = i2;
    g_w[o + 0] = r0 * s; g_w[o + 1] = r1 * s; g_w[o + 2] = r2 * s;
}

// ---------------------------------------------------------------------------
// Kernel 2: build X = concat(features1, interp(features2)) -> fp16
// ---------------------------------------------------------------------------
__global__ __launch_bounds__(384) void build_x_kernel(
    const float* __restrict__ f1, const float* __restrict__ f2)
{
    const int p = blockIdx.x;
    const int t = threadIdx.x;
    float v;

    if (t < C1DIM) {
        v = f1[(size_t)p * C1DIM + t];
    } else {
        const int c = t - C1DIM;
        const int b = p >> 14;
        const size_t o = (size_t)p * 3;
        const int i0 = g_idx[o], i1 = g_idx[o + 1], i2 = g_idx[o + 2];
        const float w0 = g_w[o], w1 = g_w[o + 1], w2 = g_w[o + 2];
        const float* base = f2 + (size_t)b * MPTS * C2DIM;
        v = w0 * base[(size_t)i0 * C2DIM + c]
          + w1 * base[(size_t)i1 * C2DIM + c]
          + w2 * base[(size_t)i2 * C2DIM + c];
    }
    g_Xh[(size_t)p * CIN + t] = __float2half_rn(v);
}

// ---------------------------------------------------------------------------
// Kernel 2b: merged weight prep — transpose [K,N]->[N,K] + fp16
// ---------------------------------------------------------------------------
__global__ void prep_w_kernel(const float* __restrict__ W1,
                              const float* __restrict__ W2,
                              const float* __restrict__ W3)
{
    int i = blockIdx.x * 256 + threadIdx.x;
    if (i < H1DIM * CIN) {
        int n = i / CIN, k = i - n * CIN;
        g_W1h[i] = __float2half_rn(W1[(size_t)k * H1DIM + n]);
    } else if (i < H1DIM * CIN + H2DIM * H1DIM) {
        int j = i - H1DIM * CIN;
        int n = j / H1DIM, k = j - n * H1DIM;
        g_W2h[j] = __float2half_rn(W2[(size_t)k * H2DIM + n]);
    } else if (i < H1DIM * CIN + H2DIM * H1DIM + COUT * H2DIM) {
        int j = i - (H1DIM * CIN + H2DIM * H1DIM);
        int n = j / H2DIM, k = j - n * H2DIM;
        g_W3h[j] = __float2half_rn(W3[(size_t)k * COUT + n]);
    }
}

// ---------------------------------------------------------------------------
// Kernel 3: single-pass fp16 GEMM, BK=64, 3-stage cp.async ring,
// ONE __syncthreads per chunk.
// C[M,Ntot] = A[M,K] @ B[Ntot,K]^T + bias (opt ReLU).
// CTA 128x128, 8 warps (4m x 2n), warp tile 32x64.
// SROW=144 (128B payload + 16B pad): conflict-free cp.async stores and
// ldmatrix reads (row-start bank 4r mod 32, distinct over 8 rows).
// outHalf: 1 = fp16 store to Ch, 0 = fp32 store to Cf.
// ---------------------------------------------------------------------------
#define BM 128
#define BN 128
#define BK 64
#define SROW 144
#define TILEB (128 * SROW)            // 18432 per operand tile
#define SBUF (2 * TILEB)              // per stage: A tile then B tile
#define SP_SMEM (3 * SBUF)            // 110592

__device__ __forceinline__ void load2(uint32_t sbuf,
                                      const __half* __restrict__ A,
                                      const __half* __restrict__ B,
                                      int K, int tid)
{
#pragma unroll
    for (int i = 0; i < 4; i++) {
        const int g = tid + i * 256;      // 0..1023
        const int row = g >> 3;           // 0..127
        const int piece = g & 7;          // 0..7 (16B each, 128B row)
        const uint32_t d = row * SROW + piece * 16;
        const size_t s = (size_t)row * K + piece * 8;
        cpa16(sbuf + d, A + s);
        cpa16(sbuf + TILEB + d, B + s);
    }
}

__global__ __launch_bounds__(256, 2) void gemm_sp(
    const __half* __restrict__ A, const __half* __restrict__ B,
    const float* __restrict__ bias,
    __half* __restrict__ Ch, float* __restrict__ Cf,
    int K, int Ntot, int doRelu, int outHalf)
{
    extern __shared__ char smem[];
    const uint32_t sb = smem_to_u32(smem);
    const int tid = threadIdx.x;
    const int wid = tid >> 5;
    const int lane = tid & 31;
    const int gid = lane >> 2;
    const int tig = lane & 3;
    const int warp_m = wid >> 1;
    const int warp_n = wid & 1;
    const int m0 = blockIdx.y * BM;
    const int n0 = blockIdx.x * BN;

    const __half* Ap = A + (size_t)m0 * K;
    const __half* Bp = B + (size_t)n0 * K;

    float acc[2][8][4];
#pragma unroll
    for (int t = 0; t < 2; t++)
#pragma unroll
        for (int nt = 0; nt < 8; nt++)
#pragma unroll
            for (int r = 0; r < 4; r++) acc[t][nt][r] = 0.0f;

    const int nch = K / BK;               // 6, 4, 4

    const uint32_t a_rel = (uint32_t)((warp_m * 32 + (lane & 15)) * SROW
                                      + ((lane >> 4) << 4));
    const uint32_t b_rel = (uint32_t)((warp_n * 64 + ((lane >> 4) << 3)
                                       + (lane & 7)) * SROW
                                      + (((lane >> 3) & 1) << 4));

    // prologue: stages for chunks 0, 1
    load2(sb + 0 * SBUF, Ap, Bp, K, tid);
    cpa_commit();
    load2(sb + 1 * SBUF, Ap + BK, Bp + BK, K, tid);
    cpa_commit();

    for (int c = 0; c < nch; c++) {
        cpa_wait<1>();                 // chunk c data complete
        __syncthreads();               // visible to all; prev compute done

        // issue chunk c+2 into the stage consumed at c-1 (safe post-barrier)
        if (c + 2 < nch)
            load2(sb + ((c + 2) % 3) * SBUF,
                  Ap + (c + 2) * BK, Bp + (c + 2) * BK, K, tid);
        cpa_commit();                  // always commit for group accounting

        const uint32_t sA = sb + (c % 3) * SBUF;
        const uint32_t sB = sA + TILEB;

#pragma unroll
        for (int s = 0; s < 4; s++) {  // four k16 steps per 64-chunk
            uint32_t aF[2][4];
#pragma unroll
            for (int t = 0; t < 2; t++)
                ldsm_x4(aF[t], sA + a_rel + t * (16 * SROW) + s * 32);
#pragma unroll
            for (int np = 0; np < 4; np++) {
                uint32_t bh[4];
                ldsm_x4(bh, sB + b_rel + np * (16 * SROW) + s * 32);
#pragma unroll
                for (int t = 0; t < 2; t++) {
                    mma_f16(acc[t][np * 2],     aF[t], bh + 0);
                    mma_f16(acc[t][np * 2 + 1], aF[t], bh + 2);
                }
            }
        }
    }

    // Epilogue: bias (+ReLU)
#pragma unroll
    for (int t = 0; t < 2; t++) {
        const int r0 = m0 + warp_m * 32 + t * 16 + gid;
        const int r1 = r0 + 8;
#pragma unroll
        for (int nt = 0; nt < 8; nt++) {
            const int col = n0 + warp_n * 64 + nt * 8 + tig * 2;
            const float bv0 = __ldg(&bias[col]);
            const float bv1 = __ldg(&bias[col + 1]);
            float v00 = acc[t][nt][0] + bv0;
            float v01 = acc[t][nt][1] + bv1;
            float v10 = acc[t][nt][2] + bv0;
            float v11 = acc[t][nt][3] + bv1;
            if (doRelu) {
                v00 = fmaxf(v00, 0.0f); v01 = fmaxf(v01, 0.0f);
                v10 = fmaxf(v10, 0.0f); v11 = fmaxf(v11, 0.0f);
            }
            if (outHalf) {
                *(__half2*)(Ch + (size_t)r0 * Ntot + col) =
                    __halves2half2(__float2half_rn(v00), __float2half_rn(v01));
                *(__half2*)(Ch + (size_t)r1 * Ntot + col) =
                    __halves2half2(__float2half_rn(v10), __float2half_rn(v11));
            } else {
                *(float2*)(Cf + (size_t)r0 * Ntot + col) = make_float2(v00, v01);
                *(float2*)(Cf + (size_t)r1 * Ntot + col) = make_float2(v10, v11);
            }
        }
    }
}

// ---------------------------------------------------------------------------
// Launch
// ---------------------------------------------------------------------------
extern "C" void kernel_launch(void* const* d_in, const int* in_sizes, int n_in,
                              void* d_out, int out_size)
{
    const float* xyz1 = (const float*)d_in[0];
    const float* xyz2 = (const float*)d_in[1];
    const float* f1   = (const float*)d_in[2];
    const float* f2   = (const float*)d_in[3];
    const float* W1   = (const float*)d_in[4];
    const float* b1   = (const float*)d_in[5];
    const float* W2   = (const float*)d_in[6];
    const float* b2   = (const float*)d_in[7];
    const float* W3   = (const float*)d_in[8];
    const float* b3   = (const float*)d_in[9];
    float* out = (float*)d_out;

    void *xh, *hah, *hbh, *w1h, *w2h, *w3h;
    cudaGetSymbolAddress(&xh,  g_Xh);
    cudaGetSymbolAddress(&hah, g_Hah);
    cudaGetSymbolAddress(&hbh, g_Hbh);
    cudaGetSymbolAddress(&w1h, g_W1h);
    cudaGetSymbolAddress(&w2h, g_W2h);
    cudaGetSymbolAddress(&w3h, g_W3h);

    __half *Xh=(__half*)xh, *Hah=(__half*)hah, *Hbh=(__half*)hbh;
    __half *W1h=(__half*)w1h, *W2h=(__half*)w2h, *W3h=(__half*)w3h;

    cudaFuncSetAttribute(gemm_sp,
                         cudaFuncAttributeMaxDynamicSharedMemorySize, SP_SMEM);

    dim3 g1(NPTS / 256, BATCH);
    three_nn_kernel<<<g1, 256>>>(xyz1, xyz2);

    build_x_kernel<<<TOTAL, 384>>>(f1, f2);

    const int prep_total = H1DIM * CIN + H2DIM * H1DIM + COUT * H2DIM;
    prep_w_kernel<<<(prep_total + 255) / 256, 256>>>(W1, W2, W3);

    gemm_sp<<<dim3(H1DIM / BN, TOTAL / BM), 256, SP_SMEM>>>(
        Xh, W1h, b1, Hah, nullptr, CIN, H1DIM, 1, 1);
    gemm_sp<<<dim3(H2DIM / BN, TOTAL / BM), 256, SP_SMEM>>>(
        Hah, W2h, b2, Hbh, nullptr, H1DIM, H2DIM, 1, 1);
    gemm_sp<<<dim3(COUT / BN, TOTAL / BM), 256, SP_SMEM>>>(
        Hbh, W3h, b3, nullptr, out, H2DIM, COUT, 0, 0);
}

// round 11
// speedup vs baseline: 1.9201x; 1.1985x over previous
#include <cuda_runtime.h>
#include <cuda_fp16.h>
#include <cstdint>

// Problem constants (fixed shapes for this dataset)
#define BATCH   4
#define NPTS    16384
#define MPTS    4096
#define C1DIM   128
#define C2DIM   256
#define CIN     384       // C1 + C2
#define H1DIM   256
#define H2DIM   256
#define COUT    128
#define TOTAL   (BATCH * NPTS)   // 65536 points

// ---------------------------------------------------------------------------
// Scratch (static device globals — no runtime allocation allowed)
// ---------------------------------------------------------------------------
__device__ int   g_idx[TOTAL * 3];
__device__ float g_w[TOTAL * 3];
__device__ __align__(256) __half g_Xh[(size_t)TOTAL * CIN];
__device__ __align__(256) __half g_Hah[(size_t)TOTAL * H1DIM];
__device__ __align__(256) __half g_Hbh[(size_t)TOTAL * H2DIM];
__device__ __align__(256) __half g_W1h[H1DIM * CIN];
__device__ __align__(256) __half g_W2h[H2DIM * H1DIM];
__device__ __align__(256) __half g_W3h[COUT * H2DIM];

// ---------------------------------------------------------------------------
// Small helpers
// ---------------------------------------------------------------------------
__device__ __forceinline__ uint32_t smem_to_u32(const void* p) {
    uint32_t a;
    asm("{ .reg .u64 t; cvta.to.shared.u64 t, %1; cvt.u32.u64 %0, t; }"
        : "=r"(a) : "l"(p));
    return a;
}
__device__ __forceinline__ void cpa16(uint32_t dst, const void* src) {
    asm volatile("cp.async.cg.shared.global [%0], [%1], 16;"
                 :: "r"(dst), "l"(src));
}
__device__ __forceinline__ void cpa_commit() {
    asm volatile("cp.async.commit_group;" ::: "memory");
}
template <int N>
__device__ __forceinline__ void cpa_wait() {
    asm volatile("cp.async.wait_group %0;" :: "n"(N) : "memory");
}
__device__ __forceinline__ void ldsm_x4(uint32_t* r, uint32_t addr) {
    asm volatile("ldmatrix.sync.aligned.m8n8.x4.shared.b16 {%0,%1,%2,%3}, [%4];"
                 : "=r"(r[0]), "=r"(r[1]), "=r"(r[2]), "=r"(r[3]) : "r"(addr));
}
// m16n8k16 row.col fp16 MMA, f32 accumulate
__device__ __forceinline__ void mma_f16(float* d, const uint32_t* a,
                                        const uint32_t* b) {
    asm("mma.sync.aligned.m16n8k16.row.col.f32.f16.f16.f32 "
        "{%0,%1,%2,%3}, {%4,%5,%6,%7}, {%8,%9}, {%0,%1,%2,%3};"
        : "+f"(d[0]), "+f"(d[1]), "+f"(d[2]), "+f"(d[3])
        : "r"(a[0]), "r"(a[1]), "r"(a[2]), "r"(a[3]), "r"(b[0]), "r"(b[1]));
}
// packed f32x2 helpers (sm_100+; proven on this harness)
__device__ __forceinline__ unsigned long long pk2(float a, float b) {
    unsigned long long r;
    asm("mov.b64 %0, {%1, %2};" : "=l"(r)
        : "r"(__float_as_uint(a)), "r"(__float_as_uint(b)));
    return r;
}
__device__ __forceinline__ unsigned long long mul2(unsigned long long a,
                                                   unsigned long long b) {
    unsigned long long r;
    asm("mul.rn.f32x2 %0, %1, %2;" : "=l"(r) : "l"(a), "l"(b));
    return r;
}
__device__ __forceinline__ unsigned long long fma2(unsigned long long a,
                                                   unsigned long long b,
                                                   unsigned long long c) {
    unsigned long long r;
    asm("fma.rn.f32x2 %0, %1, %2, %3;" : "=l"(r) : "l"(a), "l"(b), "l"(c));
    return r;
}
__device__ __forceinline__ void unpk2(unsigned long long v, float& lo, float& hi) {
    uint32_t a, b;
    asm("mov.b64 {%0, %1}, %2;" : "=r"(a), "=r"(b) : "l"(v));
    lo = __uint_as_float(a);
    hi = __uint_as_float(b);
}

// ---------------------------------------------------------------------------
// Kernel 1: three_nn via d' = |b|^2 - 2 a.b (threshold-shifted; same ordering
// as full distance, and matches the reference formula sq1+sq2-2*dots).
// 4 candidates per iteration, packed f32x2.
// Dynamic smem: 4 * MPTS floats = 64KB.
// ---------------------------------------------------------------------------
__device__ __forceinline__ void upd3(float d, int j,
                                     float& d0, float& d1, float& d2,
                                     int& i0, int& i1, int& i2) {
    if (d < d2) {
        if (d < d1) {
            d2 = d1; i2 = i1;
            if (d < d0) { d1 = d0; i1 = i0; d0 = d; i0 = j; }
            else        { d1 = d;  i1 = j; }
        } else {
            d2 = d; i2 = j;
        }
    }
}

__global__ __launch_bounds__(256) void three_nn_kernel(
    const float* __restrict__ xyz1, const float* __restrict__ xyz2)
{
    extern __shared__ __align__(16) float s3[];
    float* sbx = s3;
    float* sby = s3 + MPTS;
    float* sbz = s3 + 2 * MPTS;
    float* sbq = s3 + 3 * MPTS;   // |b|^2

    const int b = blockIdx.y;
    const float* p2 = xyz2 + (size_t)b * MPTS * 3;
    for (int j = threadIdx.x; j < MPTS; j += 256) {
        const float bx = p2[3 * j + 0];
        const float by = p2[3 * j + 1];
        const float bz = p2[3 * j + 2];
        sbx[j] = bx; sby[j] = by; sbz[j] = bz;
        sbq[j] = bx * bx + by * by + bz * bz;
    }
    __syncthreads();

    const int n = blockIdx.x * 256 + threadIdx.x;
    const float* p1 = xyz1 + ((size_t)b * NPTS + n) * 3;
    const float x = p1[0], y = p1[1], z = p1[2];
    const unsigned long long x2 = pk2(x, x);
    const unsigned long long y2 = pk2(y, y);
    const unsigned long long z2 = pk2(z, z);
    const unsigned long long n2 = pk2(-2.0f, -2.0f);

    // track d' = |b|^2 - 2 a.b   (= d - |a|^2, same ordering)
    float d0 = 1e30f, d1 = 1e30f, d2 = 1e30f;
    int   i0 = 0, i1 = 0, i2 = 0;

    const ulonglong2* bxp = (const ulonglong2*)sbx;
    const ulonglong2* byp = (const ulonglong2*)sby;
    const ulonglong2* bzp = (const ulonglong2*)sbz;
    const ulonglong2* bqp = (const ulonglong2*)sbq;

#pragma unroll 2
    for (int p = 0; p < MPTS / 4; p++) {
        const ulonglong2 cx = bxp[p];
        const ulonglong2 cy = byp[p];
        const ulonglong2 cz = bzp[p];
        const ulonglong2 cq = bqp[p];
        unsigned long long t0 = mul2(x2, cx.x);
        t0 = fma2(y2, cy.x, t0);
        t0 = fma2(z2, cz.x, t0);
        const unsigned long long dp0 = fma2(n2, t0, cq.x);
        unsigned long long t1 = mul2(x2, cx.y);
        t1 = fma2(y2, cy.y, t1);
        t1 = fma2(z2, cz.y, t1);
        const unsigned long long dp1 = fma2(n2, t1, cq.y);
        float l0, h0, l1, h1;
        unpk2(dp0, l0, h0);
        unpk2(dp1, l1, h1);
        const float m = fminf(fminf(l0, h0), fminf(l1, h1));
        if (m < d2) {
            upd3(l0, 4 * p,     d0, d1, d2, i0, i1, i2);
            upd3(h0, 4 * p + 1, d0, d1, d2, i0, i1, i2);
            upd3(l1, 4 * p + 2, d0, d1, d2, i0, i1, i2);
            upd3(h1, 4 * p + 3, d0, d1, d2, i0, i1, i2);
        }
    }

    const float sqa = x * x + y * y + z * z;
    float r0 = 1.0f / fmaxf(d0 + sqa, 1e-10f);
    float r1 = 1.0f / fmaxf(d1 + sqa, 1e-10f);
    float r2 = 1.0f / fmaxf(d2 + sqa, 1e-10f);
    float s = 1.0f / (r0 + r1 + r2);

    size_t o = ((size_t)b * NPTS + n) * 3;
    g_idx[o + 0] = i0; g_idx[o + 1] = i1; g_idx[o + 2] = i2;
    g_w[o + 0] = r0 * s; g_w[o + 1] = r1 * s; g_w[o + 2] = r2 * s;
}

// ---------------------------------------------------------------------------
// Kernel 2: build X = concat(features1, interp(features2)) -> fp16.
// 8 points per block; each thread produces 8 channels (one 16B store).
// ---------------------------------------------------------------------------
__global__ __launch_bounds__(384) void build_x_kernel(
    const float* __restrict__ f1, const float* __restrict__ f2)
{
    const int tid = threadIdx.x;
    const int pt  = tid / 48;            // 0..7
    const int ch8 = (tid - pt * 48) * 8; // 0..376
    const int p = blockIdx.x * 8 + pt;

    float v[8];
    if (ch8 < C1DIM) {
        const float* src = f1 + (size_t)p * C1DIM + ch8;
        const float4 a = *(const float4*)src;
        const float4 c = *(const float4*)(src + 4);
        v[0] = a.x; v[1] = a.y; v[2] = a.z; v[3] = a.w;
        v[4] = c.x; v[5] = c.y; v[6] = c.z; v[7] = c.w;
    } else {
        const int c = ch8 - C1DIM;
        const int bb = p >> 14;          // NPTS = 16384
        const size_t o = (size_t)p * 3;
        const int i0 = g_idx[o], i1 = g_idx[o + 1], i2 = g_idx[o + 2];
        const float w0 = g_w[o], w1 = g_w[o + 1], w2 = g_w[o + 2];
        const float* base = f2 + (size_t)bb * MPTS * C2DIM + c;
        const float* r0p = base + (size_t)i0 * C2DIM;
        const float* r1p = base + (size_t)i1 * C2DIM;
        const float* r2p = base + (size_t)i2 * C2DIM;
        const float4 a0 = *(const float4*)r0p;
        const float4 a1 = *(const float4*)(r0p + 4);
        const float4 b0 = *(const float4*)r1p;
        const float4 b1 = *(const float4*)(r1p + 4);
        const float4 c0 = *(const float4*)r2p;
        const float4 c1 = *(const float4*)(r2p + 4);
        v[0] = w0 * a0.x + w1 * b0.x + w2 * c0.x;
        v[1] = w0 * a0.y + w1 * b0.y + w2 * c0.y;
        v[2] = w0 * a0.z + w1 * b0.z + w2 * c0.z;
        v[3] = w0 * a0.w + w1 * b0.w + w2 * c0.w;
        v[4] = w0 * a1.x + w1 * b1.x + w2 * c1.x;
        v[5] = w0 * a1.y + w1 * b1.y + w2 * c1.y;
        v[6] = w0 * a1.z + w1 * b1.z + w2 * c1.z;
        v[7] = w0 * a1.w + w1 * b1.w + w2 * c1.w;
    }

    __half h[8];
#pragma unroll
    for (int k = 0; k < 8; k++) h[k] = __float2half_rn(v[k]);
    *(uint4*)(g_Xh + (size_t)p * CIN + ch8) = *(const uint4*)h;
}

// ---------------------------------------------------------------------------
// Kernel 2b: merged weight prep — transpose [K,N]->[N,K] + fp16
// ---------------------------------------------------------------------------
__global__ void prep_w_kernel(const float* __restrict__ W1,
                              const float* __restrict__ W2,
                              const float* __restrict__ W3)
{
    int i = blockIdx.x * 256 + threadIdx.x;
    if (i < H1DIM * CIN) {
        int n = i / CIN, k = i - n * CIN;
        g_W1h[i] = __float2half_rn(W1[(size_t)k * H1DIM + n]);
    } else if (i < H1DIM * CIN + H2DIM * H1DIM) {
        int j = i - H1DIM * CIN;
        int n = j / H1DIM, k = j - n * H1DIM;
        g_W2h[j] = __float2half_rn(W2[(size_t)k * H2DIM + n]);
    } else if (i < H1DIM * CIN + H2DIM * H1DIM + COUT * H2DIM) {
        int j = i - (H1DIM * CIN + H2DIM * H1DIM);
        int n = j / H2DIM, k = j - n * H2DIM;
        g_W3h[j] = __float2half_rn(W3[(size_t)k * COUT + n]);
    }
}

// ---------------------------------------------------------------------------
// Kernel 3: single-pass fp16 GEMM, BK=64, 3-stage cp.async ring,
// ONE __syncthreads per chunk; all LDSMs of a k16-step hoisted before MMAs.
// C[M,Ntot] = A[M,K] @ B[Ntot,K]^T + bias (opt ReLU).
// CTA 128x128, 8 warps (4m x 2n), warp tile 32x64. SROW=144 conflict-free.
// outHalf: 1 = fp16 store to Ch, 0 = fp32 store to Cf.
// ---------------------------------------------------------------------------
#define BM 128
#define BN 128
#define BK 64
#define SROW 144
#define TILEB (128 * SROW)            // 18432 per operand tile
#define SBUF (2 * TILEB)              // per stage: A tile then B tile
#define SP_SMEM (3 * SBUF)            // 110592

__device__ __forceinline__ void load2(uint32_t sbuf,
                                      const __half* __restrict__ A,
                                      const __half* __restrict__ B,
                                      int K, int tid)
{
#pragma unroll
    for (int i = 0; i < 4; i++) {
        const int g = tid + i * 256;      // 0..1023
        const int row = g >> 3;           // 0..127
        const int piece = g & 7;          // 0..7 (16B each, 128B row)
        const uint32_t d = row * SROW + piece * 16;
        const size_t s = (size_t)row * K + piece * 8;
        cpa16(sbuf + d, A + s);
        cpa16(sbuf + TILEB + d, B + s);
    }
}

__global__ __launch_bounds__(256, 2) void gemm_sp(
    const __half* __restrict__ A, const __half* __restrict__ B,
    const float* __restrict__ bias,
    __half* __restrict__ Ch, float* __restrict__ Cf,
    int K, int Ntot, int doRelu, int outHalf)
{
    extern __shared__ char smem[];
    const uint32_t sb = smem_to_u32(smem);
    const int tid = threadIdx.x;
    const int wid = tid >> 5;
    const int lane = tid & 31;
    const int gid = lane >> 2;
    const int tig = lane & 3;
    const int warp_m = wid >> 1;
    const int warp_n = wid & 1;
    const int m0 = blockIdx.y * BM;
    const int n0 = blockIdx.x * BN;

    const __half* Ap = A + (size_t)m0 * K;
    const __half* Bp = B + (size_t)n0 * K;

    float acc[2][8][4];
#pragma unroll
    for (int t = 0; t < 2; t++)
#pragma unroll
        for (int nt = 0; nt < 8; nt++)
#pragma unroll
            for (int r = 0; r < 4; r++) acc[t][nt][r] = 0.0f;

    const int nch = K / BK;               // 6, 4, 4

    const uint32_t a_rel = (uint32_t)((warp_m * 32 + (lane & 15)) * SROW
                                      + ((lane >> 4) << 4));
    const uint32_t b_rel = (uint32_t)((warp_n * 64 + ((lane >> 4) << 3)
                                       + (lane & 7)) * SROW
                                      + (((lane >> 3) & 1) << 4));

    // prologue: stages for chunks 0, 1
    load2(sb + 0 * SBUF, Ap, Bp, K, tid);
    cpa_commit();
    load2(sb + 1 * SBUF, Ap + BK, Bp + BK, K, tid);
    cpa_commit();

    for (int c = 0; c < nch; c++) {
        cpa_wait<1>();                 // chunk c data complete
        __syncthreads();               // visible to all; prev compute done

        // issue chunk c+2 into the stage consumed at c-1 (safe post-barrier)
        if (c + 2 < nch)
            load2(sb + ((c + 2) % 3) * SBUF,
                  Ap + (c + 2) * BK, Bp + (c + 2) * BK, K, tid);
        cpa_commit();                  // always commit for group accounting

        const uint32_t sA = sb + (c % 3) * SBUF;
        const uint32_t sB = sA + TILEB;

#pragma unroll
        for (int s = 0; s < 4; s++) {  // four k16 steps per 64-chunk
            // hoist ALL fragment loads for this step before the MMA burst
            uint32_t aF[2][4];
            uint32_t bF[4][4];
#pragma unroll
            for (int t = 0; t < 2; t++)
                ldsm_x4(aF[t], sA + a_rel + t * (16 * SROW) + s * 32);
#pragma unroll
            for (int np = 0; np < 4; np++)
                ldsm_x4(bF[np], sB + b_rel + np * (16 * SROW) + s * 32);
#pragma unroll
            for (int np = 0; np < 4; np++)
#pragma unroll
                for (int t = 0; t < 2; t++) {
                    mma_f16(acc[t][np * 2],     aF[t], bF[np] + 0);
                    mma_f16(acc[t][np * 2 + 1], aF[t], bF[np] + 2);
                }
        }
    }

    // Epilogue: bias (+ReLU)
#pragma unroll
    for (int t = 0; t < 2; t++) {
        const int r0 = m0 + warp_m * 32 + t * 16 + gid;
        const int r1 = r0 + 8;
#pragma unroll
        for (int nt = 0; nt < 8; nt++) {
            const int col = n0 + warp_n * 64 + nt * 8 + tig * 2;
            const float bv0 = __ldg(&bias[col]);
            const float bv1 = __ldg(&bias[col + 1]);
            float v00 = acc[t][nt][0] + bv0;
            float v01 = acc[t][nt][1] + bv1;
            float v10 = acc[t][nt][2] + bv0;
            float v11 = acc[t][nt][3] + bv1;
            if (doRelu) {
                v00 = fmaxf(v00, 0.0f); v01 = fmaxf(v01, 0.0f);
                v10 = fmaxf(v10, 0.0f); v11 = fmaxf(v11, 0.0f);
            }
            if (outHalf) {
                *(__half2*)(Ch + (size_t)r0 * Ntot + col) =
                    __halves2half2(__float2half_rn(v00), __float2half_rn(v01));
                *(__half2*)(Ch + (size_t)r1 * Ntot + col) =
                    __halves2half2(__float2half_rn(v10), __float2half_rn(v11));
            } else {
                *(float2*)(Cf + (size_t)r0 * Ntot + col) = make_float2(v00, v01);
                *(float2*)(Cf + (size_t)r1 * Ntot + col) = make_float2(v10, v11);
            }
        }
    }
}

// ---------------------------------------------------------------------------
// Launch
// ---------------------------------------------------------------------------
extern "C" void kernel_launch(void* const* d_in, const int* in_sizes, int n_in,
                              void* d_out, int out_size)
{
    const float* xyz1 = (const float*)d_in[0];
    const float* xyz2 = (const float*)d_in[1];
    const float* f1   = (const float*)d_in[2];
    const float* f2   = (const float*)d_in[3];
    const float* W1   = (const float*)d_in[4];
    const float* b1   = (const float*)d_in[5];
    const float* W2   = (const float*)d_in[6];
    const float* b2   = (const float*)d_in[7];
    const float* W3   = (const float*)d_in[8];
    const float* b3   = (const float*)d_in[9];
    float* out = (float*)d_out;

    void *xh, *hah, *hbh, *w1h, *w2h, *w3h;
    cudaGetSymbolAddress(&xh,  g_Xh);
    cudaGetSymbolAddress(&hah, g_Hah);
    cudaGetSymbolAddress(&hbh, g_Hbh);
    cudaGetSymbolAddress(&w1h, g_W1h);
    cudaGetSymbolAddress(&w2h, g_W2h);
    cudaGetSymbolAddress(&w3h, g_W3h);

    __half *Xh=(__half*)xh, *Hah=(__half*)hah, *Hbh=(__half*)hbh;
    __half *W1h=(__half*)w1h, *W2h=(__half*)w2h, *W3h=(__half*)w3h;

    const int nn_smem = 4 * MPTS * sizeof(float);   // 65536
    cudaFuncSetAttribute(three_nn_kernel,
                         cudaFuncAttributeMaxDynamicSharedMemorySize, nn_smem);
    cudaFuncSetAttribute(gemm_sp,
                         cudaFuncAttributeMaxDynamicSharedMemorySize, SP_SMEM);

    dim3 g1(NPTS / 256, BATCH);
    three_nn_kernel<<<g1, 256, nn_smem>>>(xyz1, xyz2);

    build_x_kernel<<<TOTAL / 8, 384>>>(f1, f2);

    const int prep_total = H1DIM * CIN + H2DIM * H1DIM + COUT * H2DIM;
    prep_w_kernel<<<(prep_total + 255) / 256, 256>>>(W1, W2, W3);

    gemm_sp<<<dim3(H1DIM / BN, TOTAL / BM), 256, SP_SMEM>>>(
        Xh, W1h, b1, Hah, nullptr, CIN, H1DIM, 1, 1);
    gemm_sp<<<dim3(H2DIM / BN, TOTAL / BM), 256, SP_SMEM>>>(
        Hah, W2h, b2, Hbh, nullptr, H1DIM, H2DIM, 1, 1);
    gemm_sp<<<dim3(COUT / BN, TOTAL / BM), 256, SP_SMEM>>>(
        Hbh, W3h, b3, nullptr, out, H2DIM, COUT, 0, 0);
}

// round 12
// speedup vs baseline: 1.9716x; 1.0268x over previous
#include <cuda_runtime.h>
#include <cuda_fp16.h>
#include <cstdint>

// Problem constants (fixed shapes for this dataset)
#define BATCH   4
#define NPTS    16384
#define MPTS    4096
#define C1DIM   128
#define C2DIM   256
#define CIN     384       // C1 + C2
#define H1DIM   256
#define H2DIM   256
#define COUT    128
#define TOTAL   (BATCH * NPTS)   // 65536 points

// ---------------------------------------------------------------------------
// Scratch (static device globals — no runtime allocation allowed)
// ---------------------------------------------------------------------------
__device__ int   g_idx[TOTAL * 3];
__device__ float g_w[TOTAL * 3];
__device__ __align__(256) __half g_Xh[(size_t)TOTAL * CIN];
__device__ __align__(256) __half g_W1h[H1DIM * CIN];
__device__ __align__(256) __half g_W2h[H2DIM * H1DIM];
__device__ __align__(256) __half g_W3h[COUT * H2DIM];

// ---------------------------------------------------------------------------
// Small helpers
// ---------------------------------------------------------------------------
__device__ __forceinline__ uint32_t smem_to_u32(const void* p) {
    uint32_t a;
    asm("{ .reg .u64 t; cvta.to.shared.u64 t, %1; cvt.u32.u64 %0, t; }"
        : "=r"(a) : "l"(p));
    return a;
}
__device__ __forceinline__ void cpa16(uint32_t dst, const void* src) {
    asm volatile("cp.async.cg.shared.global [%0], [%1], 16;"
                 :: "r"(dst), "l"(src));
}
__device__ __forceinline__ void cpa_commit() {
    asm volatile("cp.async.commit_group;" ::: "memory");
}
template <int N>
__device__ __forceinline__ void cpa_wait() {
    asm volatile("cp.async.wait_group %0;" :: "n"(N) : "memory");
}
__device__ __forceinline__ void ldsm_x4(uint32_t* r, uint32_t addr) {
    asm volatile("ldmatrix.sync.aligned.m8n8.x4.shared.b16 {%0,%1,%2,%3}, [%4];"
                 : "=r"(r[0]), "=r"(r[1]), "=r"(r[2]), "=r"(r[3]) : "r"(addr));
}
__device__ __forceinline__ void mma_f16(float* d, const uint32_t* a,
                                        const uint32_t* b) {
    asm("mma.sync.aligned.m16n8k16.row.col.f32.f16.f16.f32 "
        "{%0,%1,%2,%3}, {%4,%5,%6,%7}, {%8,%9}, {%0,%1,%2,%3};"
        : "+f"(d[0]), "+f"(d[1]), "+f"(d[2]), "+f"(d[3])
        : "r"(a[0]), "r"(a[1]), "r"(a[2]), "r"(a[3]), "r"(b[0]), "r"(b[1]));
}
__device__ __forceinline__ void sts_h2(uint32_t addr, __half a, __half b) {
    __half2 v = __halves2half2(a, b);
    asm volatile("st.shared.b32 [%0], %1;" :: "r"(addr),
                 "r"(*(const uint32_t*)&v) : "memory");
}
// packed f32x2 helpers
__device__ __forceinline__ unsigned long long pk2(float a, float b) {
    unsigned long long r;
    asm("mov.b64 %0, {%1, %2};" : "=l"(r)
        : "r"(__float_as_uint(a)), "r"(__float_as_uint(b)));
    return r;
}
__device__ __forceinline__ unsigned long long mul2(unsigned long long a,
                                                   unsigned long long b) {
    unsigned long long r;
    asm("mul.rn.f32x2 %0, %1, %2;" : "=l"(r) : "l"(a), "l"(b));
    return r;
}
__device__ __forceinline__ unsigned long long fma2(unsigned long long a,
                                                   unsigned long long b,
                                                   unsigned long long c) {
    unsigned long long r;
    asm("fma.rn.f32x2 %0, %1, %2, %3;" : "=l"(r) : "l"(a), "l"(b), "l"(c));
    return r;
}
__device__ __forceinline__ void unpk2(unsigned long long v, float& lo, float& hi) {
    uint32_t a, b;
    asm("mov.b64 {%0, %1}, %2;" : "=r"(a), "=r"(b) : "l"(v));
    lo = __uint_as_float(a);
    hi = __uint_as_float(b);
}

// ---------------------------------------------------------------------------
// Kernel 1: three_nn via d' = |b|^2 - 2 a.b (threshold-shifted; same ordering)
// ---------------------------------------------------------------------------
__device__ __forceinline__ void upd3(float d, int j,
                                     float& d0, float& d1, float& d2,
                                     int& i0, int& i1, int& i2) {
    if (d < d2) {
        if (d < d1) {
            d2 = d1; i2 = i1;
            if (d < d0) { d1 = d0; i1 = i0; d0 = d; i0 = j; }
            else        { d1 = d;  i1 = j; }
        } else {
            d2 = d; i2 = j;
        }
    }
}

__global__ __launch_bounds__(256) void three_nn_kernel(
    const float* __restrict__ xyz1, const float* __restrict__ xyz2)
{
    extern __shared__ __align__(16) float s3[];
    float* sbx = s3;
    float* sby = s3 + MPTS;
    float* sbz = s3 + 2 * MPTS;
    float* sbq = s3 + 3 * MPTS;   // |b|^2

    const int b = blockIdx.y;
    const float* p2 = xyz2 + (size_t)b * MPTS * 3;
    for (int j = threadIdx.x; j < MPTS; j += 256) {
        const float bx = p2[3 * j + 0];
        const float by = p2[3 * j + 1];
        const float bz = p2[3 * j + 2];
        sbx[j] = bx; sby[j] = by; sbz[j] = bz;
        sbq[j] = bx * bx + by * by + bz * bz;
    }
    __syncthreads();

    const int n = blockIdx.x * 256 + threadIdx.x;
    const float* p1 = xyz1 + ((size_t)b * NPTS + n) * 3;
    const float x = p1[0], y = p1[1], z = p1[2];
    const unsigned long long x2 = pk2(x, x);
    const unsigned long long y2 = pk2(y, y);
    const unsigned long long z2 = pk2(z, z);
    const unsigned long long n2 = pk2(-2.0f, -2.0f);

    float d0 = 1e30f, d1 = 1e30f, d2 = 1e30f;
    int   i0 = 0, i1 = 0, i2 = 0;

    const ulonglong2* bxp = (const ulonglong2*)sbx;
    const ulonglong2* byp = (const ulonglong2*)sby;
    const ulonglong2* bzp = (const ulonglong2*)sbz;
    const ulonglong2* bqp = (const ulonglong2*)sbq;

#pragma unroll 2
    for (int p = 0; p < MPTS / 4; p++) {
        const ulonglong2 cx = bxp[p];
        const ulonglong2 cy = byp[p];
        const ulonglong2 cz = bzp[p];
        const ulonglong2 cq = bqp[p];
        unsigned long long t0 = mul2(x2, cx.x);
        t0 = fma2(y2, cy.x, t0);
        t0 = fma2(z2, cz.x, t0);
        const unsigned long long dp0 = fma2(n2, t0, cq.x);
        unsigned long long t1 = mul2(x2, cx.y);
        t1 = fma2(y2, cy.y, t1);
        t1 = fma2(z2, cz.y, t1);
        const unsigned long long dp1 = fma2(n2, t1, cq.y);
        float l0, h0, l1, h1;
        unpk2(dp0, l0, h0);
        unpk2(dp1, l1, h1);
        const float m = fminf(fminf(l0, h0), fminf(l1, h1));
        if (m < d2) {
            upd3(l0, 4 * p,     d0, d1, d2, i0, i1, i2);
            upd3(h0, 4 * p + 1, d0, d1, d2, i0, i1, i2);
            upd3(l1, 4 * p + 2, d0, d1, d2, i0, i1, i2);
            upd3(h1, 4 * p + 3, d0, d1, d2, i0, i1, i2);
        }
    }

    const float sqa = x * x + y * y + z * z;
    float r0 = 1.0f / fmaxf(d0 + sqa, 1e-10f);
    float r1 = 1.0f / fmaxf(d1 + sqa, 1e-10f);
    float r2 = 1.0f / fmaxf(d2 + sqa, 1e-10f);
    float s = 1.0f / (r0 + r1 + r2);

    size_t o = ((size_t)b * NPTS + n) * 3;
    g_idx[o + 0] = i0; g_idx[o + 1] = i1; g_idx[o + 2] = i2;
    g_w[o + 0] = r0 * s; g_w[o + 1] = r1 * s; g_w[o + 2] = r2 * s;
}

// ---------------------------------------------------------------------------
// Kernel 2: build X = concat(features1, interp(features2)) -> fp16.
// ---------------------------------------------------------------------------
__global__ __launch_bounds__(384) void build_x_kernel(
    const float* __restrict__ f1, const float* __restrict__ f2)
{
    const int tid = threadIdx.x;
    const int pt  = tid / 48;
    const int ch8 = (tid - pt * 48) * 8;
    const int p = blockIdx.x * 8 + pt;

    float v[8];
    if (ch8 < C1DIM) {
        const float* src = f1 + (size_t)p * C1DIM + ch8;
        const float4 a = *(const float4*)src;
        const float4 c = *(const float4*)(src + 4);
        v[0] = a.x; v[1] = a.y; v[2] = a.z; v[3] = a.w;
        v[4] = c.x; v[5] = c.y; v[6] = c.z; v[7] = c.w;
    } else {
        const int c = ch8 - C1DIM;
        const int bb = p >> 14;
        const size_t o = (size_t)p * 3;
        const int i0 = g_idx[o], i1 = g_idx[o + 1], i2 = g_idx[o + 2];
        const float w0 = g_w[o], w1 = g_w[o + 1], w2 = g_w[o + 2];
        const float* base = f2 + (size_t)bb * MPTS * C2DIM + c;
        const float* r0p = base + (size_t)i0 * C2DIM;
        const float* r1p = base + (size_t)i1 * C2DIM;
        const float* r2p = base + (size_t)i2 * C2DIM;
        const float4 a0 = *(const float4*)r0p;
        const float4 a1 = *(const float4*)(r0p + 4);
        const float4 b0 = *(const float4*)r1p;
        const float4 b1 = *(const float4*)(r1p + 4);
        const float4 c0 = *(const float4*)r2p;
        const float4 c1 = *(const float4*)(r2p + 4);
        v[0] = w0 * a0.x + w1 * b0.x + w2 * c0.x;
        v[1] = w0 * a0.y + w1 * b0.y + w2 * c0.y;
        v[2] = w0 * a0.z + w1 * b0.z + w2 * c0.z;
        v[3] = w0 * a0.w + w1 * b0.w + w2 * c0.w;
        v[4] = w0 * a1.x + w1 * b1.x + w2 * c1.x;
        v[5] = w0 * a1.y + w1 * b1.y + w2 * c1.y;
        v[6] = w0 * a1.z + w1 * b1.z + w2 * c1.z;
        v[7] = w0 * a1.w + w1 * b1.w + w2 * c1.w;
    }

    __half h[8];
#pragma unroll
    for (int k = 0; k < 8; k++) h[k] = __float2half_rn(v[k]);
    *(uint4*)(g_Xh + (size_t)p * CIN + ch8) = *(const uint4*)h;
}

// ---------------------------------------------------------------------------
// Kernel 2b: merged weight prep — transpose [K,N]->[N,K] + fp16
// ---------------------------------------------------------------------------
__global__ void prep_w_kernel(const float* __restrict__ W1,
                              const float* __restrict__ W2,
                              const float* __restrict__ W3)
{
    int i = blockIdx.x * 256 + threadIdx.x;
    if (i < H1DIM * CIN) {
        int n = i / CIN, k = i - n * CIN;
        g_W1h[i] = __float2half_rn(W1[(size_t)k * H1DIM + n]);
    } else if (i < H1DIM * CIN + H2DIM * H1DIM) {
        int j = i - H1DIM * CIN;
        int n = j / H1DIM, k = j - n * H1DIM;
        g_W2h[j] = __float2half_rn(W2[(size_t)k * H2DIM + n]);
    } else if (i < H1DIM * CIN + H2DIM * H1DIM + COUT * H2DIM) {
        int j = i - (H1DIM * CIN + H2DIM * H1DIM);
        int n = j / H2DIM, k = j - n * H2DIM;
        g_W3h[j] = __float2half_rn(W3[(size_t)k * COUT + n]);
    }
}

// ---------------------------------------------------------------------------
// Kernel 3: FUSED 3-layer MLP. One CTA owns 128 rows end-to-end; H1/H2 stay
// in shared memory (no intermediate gmem traffic).
// 512 threads = 16 warps (4m x 4n), warp tile 32x64 (L1/L2), 32x32 (L3).
// fp16 single-pass HMMA, fp32 accum. 2-stage cp.async per layer.
//
// Smem map (bytes):
//   [0      .. 73728)   W ring: 2 stages x 36864 (256 rows x 144B)
//   [73728  .. 141312)  H1: 128 rows x 528B
//   [141312 .. 178176)  A ring (L1 only): 2 stages x 18432 (128 rows x 144B)
//   [141312 .. 208896)  H2 (overlays dead A ring + tail)
// ---------------------------------------------------------------------------
#define SROW   144
#define SH     528
#define WSTG   36864
#define ASTG   18432
#define OFF_W  0
#define OFF_H1 73728
#define OFF_A  141312
#define OFF_H2 141312
#define FUSED_SMEM 208896
#define NCH1   (CIN / 64)     // 6
#define NCH2   (H1DIM / 64)   // 4
#define NCH3   (H2DIM / 64)   // 4

// Load one L1 chunk: X tile rows (gmem, stride CIN) + W1 rows (stride CIN)
__device__ __forceinline__ void load_l1(uint32_t sb, int m0, int c, int tid) {
    const uint32_t adst = sb + OFF_A + (c & 1) * ASTG;
    const uint32_t wdst = sb + OFF_W + (c & 1) * WSTG;
    const int koff = c * 64;
#pragma unroll
    for (int i = 0; i < 2; i++) {            // A: 128 rows x 8 pieces
        const int g = tid + i * 512;
        const int row = g >> 3, piece = g & 7;
        cpa16(adst + row * SROW + piece * 16,
              g_Xh + (size_t)(m0 + row) * CIN + koff + piece * 8);
    }
#pragma unroll
    for (int i = 0; i < 4; i++) {            // W1: 256 rows x 8 pieces
        const int g = tid + i * 512;
        const int row = g >> 3, piece = g & 7;
        cpa16(wdst + row * SROW + piece * 16,
              g_W1h + (size_t)row * CIN + koff + piece * 8);
    }
    cpa_commit();
}
__device__ __forceinline__ void load_w2(uint32_t sb, int c, int tid) {
    const uint32_t wdst = sb + OFF_W + (c & 1) * WSTG;
    const int koff = c * 64;
#pragma unroll
    for (int i = 0; i < 4; i++) {            // W2: 256 rows x 8 pieces
        const int g = tid + i * 512;
        const int row = g >> 3, piece = g & 7;
        cpa16(wdst + row * SROW + piece * 16,
              g_W2h + (size_t)row * H1DIM + koff + piece * 8);
    }
    cpa_commit();
}
__device__ __forceinline__ void load_w3(uint32_t sb, int c, int tid) {
    const uint32_t wdst = sb + OFF_W + (c & 1) * WSTG;
    const int koff = c * 64;
#pragma unroll
    for (int i = 0; i < 2; i++) {            // W3: 128 rows x 8 pieces
        const int g = tid + i * 512;
        const int row = g >> 3, piece = g & 7;
        cpa16(wdst + row * SROW + piece * 16,
              g_W3h + (size_t)row * H2DIM + koff + piece * 8);
    }
    cpa_commit();
}

__global__ __launch_bounds__(512, 1) void fused_mlp(
    const float* __restrict__ b1, const float* __restrict__ b2,
    const float* __restrict__ b3, float* __restrict__ out)
{
    extern __shared__ char smem[];
    const uint32_t sb = smem_to_u32(smem);
    const int tid = threadIdx.x;
    const int wid = tid >> 5;
    const int lane = tid & 31;
    const int gid = lane >> 2;
    const int tig = lane & 3;
    const int warp_m = wid >> 2;          // 0..3
    const int warp_n = wid & 3;           // 0..3
    const int m0 = blockIdx.x * 128;

    // ldmatrix relative addresses
    const int lane15 = lane & 15, laneHi = lane >> 4;
    const uint32_t aRel144 = (uint32_t)((warp_m * 32 + lane15) * SROW
                                        + (laneHi << 4));
    const uint32_t aRel528 = (uint32_t)((warp_m * 32 + lane15) * SH
                                        + (laneHi << 4));
    const uint32_t bRel64 = (uint32_t)((warp_n * 64 + (laneHi << 3)
                                        + (lane & 7)) * SROW
                                       + (((lane >> 3) & 1) << 4));
    const uint32_t bRel32 = (uint32_t)((warp_n * 32 + (laneHi << 3)
                                        + (lane & 7)) * SROW
                                       + (((lane >> 3) & 1) << 4));

    float acc[2][8][4];

    // ============================ Layer 1 ============================
#pragma unroll
    for (int t = 0; t < 2; t++)
#pragma unroll
        for (int nt = 0; nt < 8; nt++)
#pragma unroll
            for (int r = 0; r < 4; r++) acc[t][nt][r] = 0.0f;

    load_l1(sb, m0, 0, tid);
    load_l1(sb, m0, 1, tid);

    for (int c = 0; c < NCH1; c++) {
        if (c + 1 < NCH1) cpa_wait<1>(); else cpa_wait<0>();
        __syncthreads();
        const uint32_t sA = sb + OFF_A + (c & 1) * ASTG;
        const uint32_t sW = sb + OFF_W + (c & 1) * WSTG;
#pragma unroll
        for (int s = 0; s < 4; s++) {
            uint32_t aF[2][4], bF[4][4];
#pragma unroll
            for (int t = 0; t < 2; t++)
                ldsm_x4(aF[t], sA + aRel144 + t * (16 * SROW) + s * 32);
#pragma unroll
            for (int np = 0; np < 4; np++)
                ldsm_x4(bF[np], sW + bRel64 + np * (16 * SROW) + s * 32);
#pragma unroll
            for (int np = 0; np < 4; np++)
#pragma unroll
                for (int t = 0; t < 2; t++) {
                    mma_f16(acc[t][np * 2],     aF[t], bF[np] + 0);
                    mma_f16(acc[t][np * 2 + 1], aF[t], bF[np] + 2);
                }
        }
        __syncthreads();
        if (c + 2 < NCH1) load_l1(sb, m0, c + 2, tid);
    }

    // Prefetch W2 stages while doing the L1 epilogue
    load_w2(sb, 0, tid);
    load_w2(sb, 1, tid);

    // L1 epilogue: bias + ReLU -> fp16 -> H1 smem
#pragma unroll
    for (int t = 0; t < 2; t++) {
        const int r0 = warp_m * 32 + t * 16 + gid;
#pragma unroll
        for (int nt = 0; nt < 8; nt++) {
            const int col = warp_n * 64 + nt * 8 + tig * 2;
            const float bv0 = __ldg(&b1[col]);
            const float bv1 = __ldg(&b1[col + 1]);
            const float v00 = fmaxf(acc[t][nt][0] + bv0, 0.0f);
            const float v01 = fmaxf(acc[t][nt][1] + bv1, 0.0f);
            const float v10 = fmaxf(acc[t][nt][2] + bv0, 0.0f);
            const float v11 = fmaxf(acc[t][nt][3] + bv1, 0.0f);
            sts_h2(sb + OFF_H1 + r0 * SH + col * 2,
                   __float2half_rn(v00), __float2half_rn(v01));
            sts_h2(sb + OFF_H1 + (r0 + 8) * SH + col * 2,
                   __float2half_rn(v10), __float2half_rn(v11));
        }
    }
    __syncthreads();   // H1 complete before L2 reads (A-ring also now dead)

    // ============================ Layer 2 ============================
#pragma unroll
    for (int t = 0; t < 2; t++)
#pragma unroll
        for (int nt = 0; nt < 8; nt++)
#pragma unroll
            for (int r = 0; r < 4; r++) acc[t][nt][r] = 0.0f;

    for (int c = 0; c < NCH2; c++) {
        if (c + 1 < NCH2) cpa_wait<1>(); else cpa_wait<0>();
        __syncthreads();
        const uint32_t sW = sb + OFF_W + (c & 1) * WSTG;
        const uint32_t aBase = sb + OFF_H1 + aRel528 + c * 128;
#pragma unroll
        for (int s = 0; s < 4; s++) {
            uint32_t aF[2][4], bF[4][4];
#pragma unroll
            for (int t = 0; t < 2; t++)
                ldsm_x4(aF[t], aBase + t * (16 * SH) + s * 32);
#pragma unroll
            for (int np = 0; np < 4; np++)
                ldsm_x4(bF[np], sW + bRel64 + np * (16 * SROW) + s * 32);
#pragma unroll
            for (int np = 0; np < 4; np++)
#pragma unroll
                for (int t = 0; t < 2; t++) {
                    mma_f16(acc[t][np * 2],     aF[t], bF[np] + 0);
                    mma_f16(acc[t][np * 2 + 1], aF[t], bF[np] + 2);
                }
        }
        __syncthreads();
        if (c + 2 < NCH2) load_w2(sb, c + 2, tid);
    }

    // Prefetch W3 stages while doing the L2 epilogue
    load_w3(sb, 0, tid);
    load_w3(sb, 1, tid);

    // L2 epilogue: bias + ReLU -> fp16 -> H2 smem
#pragma unroll
    for (int t = 0; t < 2; t++) {
        const int r0 = warp_m * 32 + t * 16 + gid;
#pragma unroll
        for (int nt = 0; nt < 8; nt++) {
            const int col = warp_n * 64 + nt * 8 + tig * 2;
            const float bv0 = __ldg(&b2[col]);
            const float bv1 = __ldg(&b2[col + 1]);
            const float v00 = fmaxf(acc[t][nt][0] + bv0, 0.0f);
            const float v01 = fmaxf(acc[t][nt][1] + bv1, 0.0f);
            const float v10 = fmaxf(acc[t][nt][2] + bv0, 0.0f);
            const float v11 = fmaxf(acc[t][nt][3] + bv1, 0.0f);
            sts_h2(sb + OFF_H2 + r0 * SH + col * 2,
                   __float2half_rn(v00), __float2half_rn(v01));
            sts_h2(sb + OFF_H2 + (r0 + 8) * SH + col * 2,
                   __float2half_rn(v10), __float2half_rn(v11));
        }
    }
    __syncthreads();   // H2 complete before L3 reads

    // ============================ Layer 3 ============================
    // warp tile 32x32: warp grid 4m x 4n covers 128 x 128
    float acc3[2][4][4];
#pragma unroll
    for (int t = 0; t < 2; t++)
#pragma unroll
        for (int nt = 0; nt < 4; nt++)
#pragma unroll
            for (int r = 0; r < 4; r++) acc3[t][nt][r] = 0.0f;

    for (int c = 0; c < NCH3; c++) {
        if (c + 1 < NCH3) cpa_wait<1>(); else cpa_wait<0>();
        __syncthreads();
        const uint32_t sW = sb + OFF_W + (c & 1) * WSTG;
        const uint32_t aBase = sb + OFF_H2 + aRel528 + c * 128;
#pragma unroll
        for (int s = 0; s < 4; s++) {
            uint32_t aF[2][4], bF[2][4];
#pragma unroll
            for (int t = 0; t < 2; t++)
                ldsm_x4(aF[t], aBase + t * (16 * SH) + s * 32);
#pragma unroll
            for (int np = 0; np < 2; np++)
                ldsm_x4(bF[np], sW + bRel32 + np * (16 * SROW) + s * 32);
#pragma unroll
            for (int np = 0; np < 2; np++)
#pragma unroll
                for (int t = 0; t < 2; t++) {
                    mma_f16(acc3[t][np * 2],     aF[t], bF[np] + 0);
                    mma_f16(acc3[t][np * 2 + 1], aF[t], bF[np] + 2);
                }
        }
        __syncthreads();
        if (c + 2 < NCH3) load_w3(sb, c + 2, tid);
    }

    // L3 epilogue: bias -> fp32 gmem
#pragma unroll
    for (int t = 0; t < 2; t++) {
        const int r0 = m0 + warp_m * 32 + t * 16 + gid;
        const int r1 = r0 + 8;
#pragma unroll
        for (int nt = 0; nt < 4; nt++) {
            const int col = warp_n * 32 + nt * 8 + tig * 2;
            const float bv0 = __ldg(&b3[col]);
            const float bv1 = __ldg(&b3[col + 1]);
            *(float2*)(out + (size_t)r0 * COUT + col) =
                make_float2(acc3[t][nt][0] + bv0, acc3[t][nt][1] + bv1);
            *(float2*)(out + (size_t)r1 * COUT + col) =
                make_float2(acc3[t][nt][2] + bv0, acc3[t][nt][3] + bv1);
        }
    }
}

// ---------------------------------------------------------------------------
// Launch
// ---------------------------------------------------------------------------
extern "C" void kernel_launch(void* const* d_in, const int* in_sizes, int n_in,
                              void* d_out, int out_size)
{
    const float* xyz1 = (const float*)d_in[0];
    const float* xyz2 = (const float*)d_in[1];
    const float* f1   = (const float*)d_in[2];
    const float* f2   = (const float*)d_in[3];
    const float* W1   = (const float*)d_in[4];
    const float* b1   = (const float*)d_in[5];
    const float* W2   = (const float*)d_in[6];
    const float* b2   = (const float*)d_in[7];
    const float* W3   = (const float*)d_in[8];
    const float* b3   = (const float*)d_in[9];
    float* out = (float*)d_out;

    const int nn_smem = 4 * MPTS * sizeof(float);   // 65536
    cudaFuncSetAttribute(three_nn_kernel,
                         cudaFuncAttributeMaxDynamicSharedMemorySize, nn_smem);
    cudaFuncSetAttribute(fused_mlp,
                         cudaFuncAttributeMaxDynamicSharedMemorySize,
                         FUSED_SMEM);

    const int prep_total = H1DIM * CIN + H2DIM * H1DIM + COUT * H2DIM;
    prep_w_kernel<<<(prep_total + 255) / 256, 256>>>(W1, W2, W3);

    dim3 g1(NPTS / 256, BATCH);
    three_nn_kernel<<<g1, 256, nn_smem>>>(xyz1, xyz2);

    build_x_kernel<<<TOTAL / 8, 384>>>(f1, f2);

    fused_mlp<<<TOTAL / 128, 512, FUSED_SMEM>>>(b1, b2, b3, out);
}